// round 2
// baseline (speedup 1.0000x reference)
#include <cuda_runtime.h>
#include <cstring>

// ---------------------------------------------------------------------------
// SimpleMaxViTBlock: LN1 -> per-token head-mixing "attention" -> +res
//                    -> LN2 -> FFN -> +res
// x: [16, 64, 64, 256] fp32.  Tokens = 65536, DIM=256, HEADS=8, HD=32, FFN=1024
//
// NOTE: the reference einsum 'bnhd,bngd->bnhg' attends ACROSS HEADS per token
// (8x8 softmax per token), not across window tokens. Window partitioning is a
// computational no-op.
// ---------------------------------------------------------------------------

constexpr int TOKENS = 16 * 64 * 64;   // 65536
constexpr int DIM    = 256;
constexpr int HEADS  = 8;
constexpr int HD     = 32;
constexpr int FFNDIM = 1024;

// Scratch (device globals: allocation-free rule)
__device__ float g_xn  [ (size_t)TOKENS * DIM    ];
__device__ float g_qkv [ (size_t)TOKENS * 3*DIM  ];
__device__ float g_attn[ (size_t)TOKENS * DIM    ];
__device__ float g_y   [ (size_t)TOKENS * DIM    ];
__device__ float g_h   [ (size_t)TOKENS * FFNDIM ];

// ---------------------------------------------------------------------------
// LayerNorm: one warp per row of 256 floats
// ---------------------------------------------------------------------------
__global__ void __launch_bounds__(256) ln_kernel(
    const float* __restrict__ x, const float* __restrict__ g,
    const float* __restrict__ b, float* __restrict__ out)
{
    int row  = (blockIdx.x * blockDim.x + threadIdx.x) >> 5;
    int lane = threadIdx.x & 31;
    const float4* xr = (const float4*)(x + (size_t)row * DIM);
    float4 v0 = xr[lane];
    float4 v1 = xr[lane + 32];

    float s = v0.x + v0.y + v0.z + v0.w + v1.x + v1.y + v1.z + v1.w;
    float q = v0.x*v0.x + v0.y*v0.y + v0.z*v0.z + v0.w*v0.w
            + v1.x*v1.x + v1.y*v1.y + v1.z*v1.z + v1.w*v1.w;
#pragma unroll
    for (int o = 16; o > 0; o >>= 1) {
        s += __shfl_xor_sync(0xffffffffu, s, o);
        q += __shfl_xor_sync(0xffffffffu, q, o);
    }
    float mean = s * (1.0f / 256.0f);
    float var  = q * (1.0f / 256.0f) - mean * mean;
    float inv  = rsqrtf(var + 1e-5f);

    const float4* g4 = (const float4*)g;
    const float4* b4 = (const float4*)b;
    float4 ga = g4[lane], gb = g4[lane + 32];
    float4 ba = b4[lane], bb = b4[lane + 32];

    float4 o0, o1;
    o0.x = (v0.x - mean) * inv * ga.x + ba.x;
    o0.y = (v0.y - mean) * inv * ga.y + ba.y;
    o0.z = (v0.z - mean) * inv * ga.z + ba.z;
    o0.w = (v0.w - mean) * inv * ga.w + ba.w;
    o1.x = (v1.x - mean) * inv * gb.x + bb.x;
    o1.y = (v1.y - mean) * inv * gb.y + bb.y;
    o1.z = (v1.z - mean) * inv * gb.z + bb.z;
    o1.w = (v1.w - mean) * inv * gb.w + bb.w;

    float4* orow = (float4*)(out + (size_t)row * DIM);
    orow[lane]      = o0;
    orow[lane + 32] = o1;
}

// ---------------------------------------------------------------------------
// GEMM (NT): C[m,n] = epilogue( sum_k A[m,k]*B[n,k] + bias[n]  [+ res[m,n]] )
// 128x128 tile, BK=8, 256 threads, 8x8 per thread with packed f32x2 FFMA.
// MODE: 0 = bias, 1 = bias+relu, 2 = bias+residual
// ---------------------------------------------------------------------------
template<int MODE>
__global__ void __launch_bounds__(256) gemm_nt(
    const float* __restrict__ A, const float* __restrict__ B,
    const float* __restrict__ bias, const float* __restrict__ res,
    float* __restrict__ C, int M, int N, int K)
{
    __shared__ __align__(16) float As[8][128];
    __shared__ __align__(16) float Bs[8][128];

    const int bm  = blockIdx.y * 128;
    const int bn  = blockIdx.x * 128;
    const int tid = threadIdx.x;

    const int lrow = tid >> 1;          // 0..127
    const int lk   = (tid & 1) * 4;     // 0 or 4

    const float* Ab = A + (size_t)(bm + lrow) * K + lk;
    const float* Bb = B + (size_t)(bn + lrow) * K + lk;

    const int ty = tid >> 4;   // 0..15 -> rows  ty*8..ty*8+7
    const int tx = tid & 15;   // 0..15 -> cols  tx*8..tx*8+7

    unsigned long long acc[8][4];
#pragma unroll
    for (int i = 0; i < 8; i++)
#pragma unroll
        for (int jp = 0; jp < 4; jp++) acc[i][jp] = 0ull;

    for (int k0 = 0; k0 < K; k0 += 8) {
        float4 a4 = *(const float4*)(Ab + k0);
        float4 b4 = *(const float4*)(Bb + k0);
        __syncthreads();
        As[lk + 0][lrow] = a4.x;  As[lk + 1][lrow] = a4.y;
        As[lk + 2][lrow] = a4.z;  As[lk + 3][lrow] = a4.w;
        Bs[lk + 0][lrow] = b4.x;  Bs[lk + 1][lrow] = b4.y;
        Bs[lk + 2][lrow] = b4.z;  Bs[lk + 3][lrow] = b4.w;
        __syncthreads();

#pragma unroll
        for (int k = 0; k < 8; k++) {
            unsigned long long bp[4];
#pragma unroll
            for (int jp = 0; jp < 4; jp++)
                bp[jp] = *(const unsigned long long*)&Bs[k][tx * 8 + jp * 2];
#pragma unroll
            for (int i = 0; i < 8; i++) {
                unsigned int au = __float_as_uint(As[k][ty * 8 + i]);
                unsigned long long ap;
                asm("mov.b64 %0, {%1, %1};" : "=l"(ap) : "r"(au));
#pragma unroll
                for (int jp = 0; jp < 4; jp++)
                    asm("fma.rn.f32x2 %0, %1, %2, %3;"
                        : "=l"(acc[i][jp])
                        : "l"(ap), "l"(bp[jp]), "l"(acc[i][jp]));
            }
        }
    }

#pragma unroll
    for (int i = 0; i < 8; i++) {
        const int m = bm + ty * 8 + i;
#pragma unroll
        for (int jp = 0; jp < 4; jp++) {
            const int n = bn + tx * 8 + jp * 2;
            float2 v;
            memcpy(&v, &acc[i][jp], 8);
            v.x += bias[n];
            v.y += bias[n + 1];
            if (MODE == 1) { v.x = fmaxf(v.x, 0.0f); v.y = fmaxf(v.y, 0.0f); }
            if (MODE == 2) {
                const float2 r = *(const float2*)&res[(size_t)m * N + n];
                v.x += r.x; v.y += r.y;
            }
            *(float2*)&C[(size_t)m * N + n] = v;
        }
    }
}

// ---------------------------------------------------------------------------
// Per-token head-mixing attention.
// For each token: scores[h,g] = (q_h . k_g)/sqrt(32); softmax over g;
// out_h = sum_g p[h,g] * v_g.
// Block: 128 threads = 16 tokens x 8 head-threads.
// qkv row layout (768 floats): [s in {q,k,v}][head 0..7][d 0..31]
// ---------------------------------------------------------------------------
__global__ void __launch_bounds__(128) attn_kernel(
    const float* __restrict__ qkv, float* __restrict__ out)
{
    __shared__ __align__(16) float ks[16][HEADS][HD + 1];
    __shared__ __align__(16) float vs[16][HEADS][HD + 1];

    const int tok0 = blockIdx.x * 16;
    const int tid  = threadIdx.x;

    // cooperative load of K and V for 16 tokens: 16*256 floats each
    // 128 threads x 8 float4 per array
    {
        // flat float4 index over [16 tokens][64 float4 of K region]
#pragma unroll
        for (int it = 0; it < 8; it++) {
            int fi  = tid + it * 128;          // 0..1023
            int t   = fi >> 6;                 // token 0..15
            int q4  = fi & 63;                 // float4 index within 256 floats
            int g   = q4 >> 3;                 // head
            int d   = (q4 & 7) * 4;            // dim
            const float* base = qkv + (size_t)(tok0 + t) * 768;
            float4 kv = *(const float4*)(base + 256 + g * HD + d);
            float4 vv = *(const float4*)(base + 512 + g * HD + d);
            ks[t][g][d] = kv.x; ks[t][g][d+1] = kv.y;
            ks[t][g][d+2] = kv.z; ks[t][g][d+3] = kv.w;
            vs[t][g][d] = vv.x; vs[t][g][d+1] = vv.y;
            vs[t][g][d+2] = vv.z; vs[t][g][d+3] = vv.w;
        }
    }
    __syncthreads();

    const int t = tid >> 3;      // local token
    const int h = tid & 7;       // head owned by this thread
    const size_t row = (size_t)(tok0 + t);

    float q[HD];
    {
        const float* qrow = qkv + row * 768 + h * HD;
#pragma unroll
        for (int d = 0; d < HD; d += 4) {
            float4 qv = *(const float4*)(qrow + d);
            q[d] = qv.x; q[d+1] = qv.y; q[d+2] = qv.z; q[d+3] = qv.w;
        }
    }

    const float scale = 0.17677669529663688f;   // 1/sqrt(32)
    float sc[HEADS];
    float mx = -1e30f;
#pragma unroll
    for (int g = 0; g < HEADS; g++) {
        float s = 0.0f;
#pragma unroll
        for (int d = 0; d < HD; d++) s += q[d] * ks[t][g][d];
        s *= scale;
        sc[g] = s;
        mx = fmaxf(mx, s);
    }
    float sum = 0.0f;
#pragma unroll
    for (int g = 0; g < HEADS; g++) {
        float e = __expf(sc[g] - mx);
        sc[g] = e;
        sum += e;
    }
    const float inv = 1.0f / sum;

    float acc[HD];
#pragma unroll
    for (int d = 0; d < HD; d++) acc[d] = 0.0f;
#pragma unroll
    for (int g = 0; g < HEADS; g++) {
        const float p = sc[g];
#pragma unroll
        for (int d = 0; d < HD; d++) acc[d] += p * vs[t][g][d];
    }

    float* orow = out + row * DIM + h * HD;
#pragma unroll
    for (int d = 0; d < HD; d += 4) {
        float4 o;
        o.x = acc[d]   * inv; o.y = acc[d+1] * inv;
        o.z = acc[d+2] * inv; o.w = acc[d+3] * inv;
        *(float4*)(orow + d) = o;
    }
}

// ---------------------------------------------------------------------------
// Launch
// ---------------------------------------------------------------------------
extern "C" void kernel_launch(void* const* d_in, const int* in_sizes, int n_in,
                              void* d_out, int out_size)
{
    const float* x      = (const float*)d_in[0];
    const float* ln1_g  = (const float*)d_in[1];
    const float* ln1_b  = (const float*)d_in[2];
    const float* qkv_w  = (const float*)d_in[3];
    const float* qkv_b  = (const float*)d_in[4];
    const float* proj_w = (const float*)d_in[5];
    const float* proj_b = (const float*)d_in[6];
    const float* ln2_g  = (const float*)d_in[7];
    const float* ln2_b  = (const float*)d_in[8];
    const float* ffn_w1 = (const float*)d_in[9];
    const float* ffn_b1 = (const float*)d_in[10];
    const float* ffn_w2 = (const float*)d_in[11];
    const float* ffn_b2 = (const float*)d_in[12];

    float *xn, *qkv, *attn, *y, *h;
    cudaGetSymbolAddress((void**)&xn,   g_xn);
    cudaGetSymbolAddress((void**)&qkv,  g_qkv);
    cudaGetSymbolAddress((void**)&attn, g_attn);
    cudaGetSymbolAddress((void**)&y,    g_y);
    cudaGetSymbolAddress((void**)&h,    g_h);

    float* out = (float*)d_out;

    // 1) LN1
    ln_kernel<<<TOKENS / 8, 256>>>(x, ln1_g, ln1_b, xn);
    // 2) QKV = xn @ qkv_w^T + qkv_b          [65536, 768]
    gemm_nt<0><<<dim3(768 / 128, TOKENS / 128), 256>>>(
        xn, qkv_w, qkv_b, nullptr, qkv, TOKENS, 3 * DIM, DIM);
    // 3) per-token head-mixing attention     [65536, 256]
    attn_kernel<<<TOKENS / 16, 128>>>(qkv, attn);
    // 4) y = x + attn @ proj_w^T + proj_b
    gemm_nt<2><<<dim3(DIM / 128, TOKENS / 128), 256>>>(
        attn, proj_w, proj_b, x, y, TOKENS, DIM, DIM);
    // 5) LN2
    ln_kernel<<<TOKENS / 8, 256>>>(y, ln2_g, ln2_b, xn);
    // 6) h = relu(xn @ ffn_w1^T + ffn_b1)    [65536, 1024]
    gemm_nt<1><<<dim3(FFNDIM / 128, TOKENS / 128), 256>>>(
        xn, ffn_w1, ffn_b1, nullptr, h, TOKENS, FFNDIM, DIM);
    // 7) out = y + h @ ffn_w2^T + ffn_b2
    gemm_nt<2><<<dim3(DIM / 128, TOKENS / 128), 256>>>(
        h, ffn_w2, ffn_b2, y, out, TOKENS, DIM, FFNDIM);
}

// round 4
// speedup vs baseline: 2.7352x; 2.7352x over previous
#include <cuda_runtime.h>
#include <cstdint>
#include <cstring>

// ---------------------------------------------------------------------------
// SimpleMaxViTBlock: LN1 -> per-token head-mixing attention -> +res
//                    -> LN2 -> FFN -> +res
// x: [16,64,64,256] fp32. Tokens=65536, DIM=256, HEADS=8, HD=32, FFN=1024.
// GEMMs: legacy mma.sync m16n8k8 tf32 (sm_80+ path; tcgen05 is blocked by the
// harness's plain sm_103 PTX target). Inputs RN-rounded to tf32, fp32 accum.
// ---------------------------------------------------------------------------

constexpr int TOKENS = 65536;
constexpr int DIM    = 256;
constexpr int HEADS  = 8;
constexpr int HD     = 32;
constexpr int FFNDIM = 1024;

// Scratch (device globals: allocation-free rule)
__device__ float g_xn  [ (size_t)TOKENS * DIM    ];
__device__ float g_qkv [ (size_t)TOKENS * 3*DIM  ];
__device__ float g_attn[ (size_t)TOKENS * DIM    ];
__device__ float g_y   [ (size_t)TOKENS * DIM    ];
__device__ float g_h   [ (size_t)TOKENS * FFNDIM ];

// ===================== helpers ==============================================
__device__ __forceinline__ uint32_t smem_u32(const void* p) {
    uint32_t a;
    asm("{ .reg .u64 t; cvta.to.shared.u64 t, %1; cvt.u32.u64 %0, t; }"
        : "=r"(a) : "l"(p));
    return a;
}
__device__ __forceinline__ uint32_t f2tf32(float x) {
    uint32_t r;
    asm("cvt.rna.tf32.f32 %0, %1;" : "=r"(r) : "f"(x));
    return r;
}
__device__ __forceinline__ void cp_async16(uint32_t saddr, const void* gaddr) {
    asm volatile("cp.async.cg.shared.global [%0], [%1], 16;"
                 :: "r"(saddr), "l"(gaddr) : "memory");
}
__device__ __forceinline__ void cp_commit() {
    asm volatile("cp.async.commit_group;" ::: "memory");
}
template<int N>
__device__ __forceinline__ void cp_wait() {
    asm volatile("cp.async.wait_group %0;" :: "n"(N) : "memory");
}
__device__ __forceinline__ void mma_tf32(
    float& d0, float& d1, float& d2, float& d3,
    uint32_t a0, uint32_t a1, uint32_t a2, uint32_t a3,
    uint32_t b0, uint32_t b1)
{
    asm volatile(
        "mma.sync.aligned.m16n8k8.row.col.f32.tf32.tf32.f32 "
        "{%0,%1,%2,%3}, {%4,%5,%6,%7}, {%8,%9}, {%0,%1,%2,%3};"
        : "+f"(d0), "+f"(d1), "+f"(d2), "+f"(d3)
        : "r"(a0), "r"(a1), "r"(a2), "r"(a3), "r"(b0), "r"(b1));
}

// ===================== tf32 mma.sync GEMM ===================================
// C[m,n] = epi( sum_k A[m,k]*B[n,k] + bias[n] [+res] ), A:[M,K], B:[N,K] rowmaj
// CTA: 128x128, BK=32, double-buffered cp.async. 8 warps (4M x 2N), warp 32x64.
// MODE: 0=bias, 1=bias+relu, 2=bias+residual
constexpr int TILE   = 128;
constexpr int BK     = 32;
constexpr int LDP    = 36;                       // padded k-stride (floats)
constexpr int SLAB   = TILE * LDP;               // floats per stage per matrix
constexpr int GEMM_SMEM = 2 * 2 * SLAB * 4;      // 73728 B

template<int MODE>
__global__ void __launch_bounds__(256) mma_gemm(
    const float* __restrict__ A, const float* __restrict__ B,
    const float* __restrict__ bias, const float* __restrict__ res,
    float* __restrict__ C, int K, int N)
{
    extern __shared__ float sm[];
    float* As = sm;                 // [2][128][36]
    float* Bs = sm + 2 * SLAB;      // [2][128][36]
    const uint32_t As_u = smem_u32(As);
    const uint32_t Bs_u = smem_u32(Bs);

    const int tid  = threadIdx.x;
    const int wid  = tid >> 5;
    const int lane = tid & 31;
    const int gid  = lane >> 2;     // 0..7
    const int tg   = lane & 3;      // 0..3

    const int bm = blockIdx.y * TILE;
    const int bn = blockIdx.x * TILE;
    const int m_off = (wid >> 1) * 32;   // warp M offset (0,32,64,96)
    const int n_off = (wid & 1) * 64;    // warp N offset (0,64)

    // cp.async mapping: fi = tid + it*256 over 1024 float4 per matrix
    const int crow = tid >> 3;          // changes per it by +32
    const int cc4  = (tid & 7) * 4;     // float offset within 32-float row

    float d[2][8][4];
#pragma unroll
    for (int mt = 0; mt < 2; mt++)
#pragma unroll
        for (int nt = 0; nt < 8; nt++)
#pragma unroll
            for (int j = 0; j < 4; j++) d[mt][nt][j] = 0.0f;

    const int C_CHUNKS = K / BK;

    // ---- issue stage 0 ----
    {
#pragma unroll
        for (int it = 0; it < 4; it++) {
            int row = crow + it * 32;
            cp_async16(As_u + (uint32_t)(row * LDP + cc4) * 4,
                       A + (size_t)(bm + row) * K + cc4);
            cp_async16(Bs_u + (uint32_t)(row * LDP + cc4) * 4,
                       B + (size_t)(bn + row) * K + cc4);
        }
        cp_commit();
    }

    for (int c = 0; c < C_CHUNKS; c++) {
        const int buf = c & 1;
        if (c + 1 < C_CHUNKS) {
            const int nb = (c + 1) & 1;
            const int k0g = (c + 1) * BK;
#pragma unroll
            for (int it = 0; it < 4; it++) {
                int row = crow + it * 32;
                cp_async16(As_u + (uint32_t)((nb * SLAB + row * LDP + cc4) * 4),
                           A + (size_t)(bm + row) * K + k0g + cc4);
                cp_async16(Bs_u + (uint32_t)((nb * SLAB + row * LDP + cc4) * 4),
                           B + (size_t)(bn + row) * K + k0g + cc4);
            }
            cp_commit();
            cp_wait<1>();
        } else {
            cp_wait<0>();
        }
        __syncthreads();

        const float* Ab = As + buf * SLAB;
        const float* Bb = Bs + buf * SLAB;

#pragma unroll
        for (int ks = 0; ks < 4; ks++) {
            const int k0 = ks * 8;
            uint32_t a[2][4];
#pragma unroll
            for (int mt = 0; mt < 2; mt++) {
                const int r0 = m_off + mt * 16 + gid;
                a[mt][0] = f2tf32(Ab[(r0)     * LDP + k0 + tg]);
                a[mt][1] = f2tf32(Ab[(r0 + 8) * LDP + k0 + tg]);
                a[mt][2] = f2tf32(Ab[(r0)     * LDP + k0 + tg + 4]);
                a[mt][3] = f2tf32(Ab[(r0 + 8) * LDP + k0 + tg + 4]);
            }
            uint32_t b[8][2];
#pragma unroll
            for (int nt = 0; nt < 8; nt++) {
                const int c0 = n_off + nt * 8 + gid;
                b[nt][0] = f2tf32(Bb[c0 * LDP + k0 + tg]);
                b[nt][1] = f2tf32(Bb[c0 * LDP + k0 + tg + 4]);
            }
#pragma unroll
            for (int mt = 0; mt < 2; mt++)
#pragma unroll
                for (int nt = 0; nt < 8; nt++)
                    mma_tf32(d[mt][nt][0], d[mt][nt][1], d[mt][nt][2], d[mt][nt][3],
                             a[mt][0], a[mt][1], a[mt][2], a[mt][3],
                             b[nt][0], b[nt][1]);
        }
        __syncthreads();
    }

    // ---- epilogue ----
#pragma unroll
    for (int nt = 0; nt < 8; nt++) {
        const int n = bn + n_off + nt * 8 + 2 * tg;
        const float2 bv = *(const float2*)&bias[n];
#pragma unroll
        for (int mt = 0; mt < 2; mt++) {
            const int m0 = bm + m_off + mt * 16 + gid;
#pragma unroll
            for (int half = 0; half < 2; half++) {
                const int m = m0 + half * 8;
                float2 v;
                v.x = d[mt][nt][half * 2 + 0] + bv.x;
                v.y = d[mt][nt][half * 2 + 1] + bv.y;
                if (MODE == 1) { v.x = fmaxf(v.x, 0.f); v.y = fmaxf(v.y, 0.f); }
                if (MODE == 2) {
                    const float2 r = *(const float2*)&res[(size_t)m * N + n];
                    v.x += r.x; v.y += r.y;
                }
                *(float2*)&C[(size_t)m * N + n] = v;
            }
        }
    }
}

// ===================== LayerNorm (one warp per 256-float row) ===============
__global__ void __launch_bounds__(256) ln_kernel(
    const float* __restrict__ x, const float* __restrict__ g,
    const float* __restrict__ b, float* __restrict__ out)
{
    int row  = (blockIdx.x * blockDim.x + threadIdx.x) >> 5;
    int lane = threadIdx.x & 31;
    const float4* xr = (const float4*)(x + (size_t)row * DIM);
    float4 v0 = xr[lane];
    float4 v1 = xr[lane + 32];

    float s = v0.x + v0.y + v0.z + v0.w + v1.x + v1.y + v1.z + v1.w;
    float q = v0.x*v0.x + v0.y*v0.y + v0.z*v0.z + v0.w*v0.w
            + v1.x*v1.x + v1.y*v1.y + v1.z*v1.z + v1.w*v1.w;
#pragma unroll
    for (int o = 16; o > 0; o >>= 1) {
        s += __shfl_xor_sync(0xffffffffu, s, o);
        q += __shfl_xor_sync(0xffffffffu, q, o);
    }
    float mean = s * (1.0f / 256.0f);
    float var  = q * (1.0f / 256.0f) - mean * mean;
    float inv  = rsqrtf(var + 1e-5f);

    const float4* g4 = (const float4*)g;
    const float4* b4 = (const float4*)b;
    float4 ga = g4[lane], gb = g4[lane + 32];
    float4 ba = b4[lane], bb = b4[lane + 32];

    float4 o0, o1;
    o0.x = (v0.x - mean) * inv * ga.x + ba.x;
    o0.y = (v0.y - mean) * inv * ga.y + ba.y;
    o0.z = (v0.z - mean) * inv * ga.z + ba.z;
    o0.w = (v0.w - mean) * inv * ga.w + ba.w;
    o1.x = (v1.x - mean) * inv * gb.x + bb.x;
    o1.y = (v1.y - mean) * inv * gb.y + bb.y;
    o1.z = (v1.z - mean) * inv * gb.z + bb.z;
    o1.w = (v1.w - mean) * inv * gb.w + bb.w;

    float4* orow = (float4*)(out + (size_t)row * DIM);
    orow[lane]      = o0;
    orow[lane + 32] = o1;
}

// ===================== Per-token head-mixing attention ======================
__global__ void __launch_bounds__(128) attn_kernel(
    const float* __restrict__ qkv, float* __restrict__ out)
{
    __shared__ __align__(16) float ks[16][HEADS][HD + 1];
    __shared__ __align__(16) float vs[16][HEADS][HD + 1];

    const int tok0 = blockIdx.x * 16;
    const int tid  = threadIdx.x;

#pragma unroll
    for (int it = 0; it < 8; it++) {
        int fi  = tid + it * 128;
        int t   = fi >> 6;
        int q4  = fi & 63;
        int g   = q4 >> 3;
        int d   = (q4 & 7) * 4;
        const float* base = qkv + (size_t)(tok0 + t) * 768;
        float4 kv = *(const float4*)(base + 256 + g * HD + d);
        float4 vv = *(const float4*)(base + 512 + g * HD + d);
        ks[t][g][d] = kv.x; ks[t][g][d+1] = kv.y;
        ks[t][g][d+2] = kv.z; ks[t][g][d+3] = kv.w;
        vs[t][g][d] = vv.x; vs[t][g][d+1] = vv.y;
        vs[t][g][d+2] = vv.z; vs[t][g][d+3] = vv.w;
    }
    __syncthreads();

    const int t = tid >> 3;
    const int h = tid & 7;
    const size_t row = (size_t)(tok0 + t);

    float q[HD];
    const float* qrow = qkv + row * 768 + h * HD;
#pragma unroll
    for (int d = 0; d < HD; d += 4) {
        float4 qv = *(const float4*)(qrow + d);
        q[d] = qv.x; q[d+1] = qv.y; q[d+2] = qv.z; q[d+3] = qv.w;
    }

    const float scale = 0.17677669529663688f;   // 1/sqrt(32)
    float sc[HEADS];
    float mx = -1e30f;
#pragma unroll
    for (int g = 0; g < HEADS; g++) {
        float s = 0.0f;
#pragma unroll
        for (int d = 0; d < HD; d++) s += q[d] * ks[t][g][d];
        s *= scale;
        sc[g] = s;
        mx = fmaxf(mx, s);
    }
    float sum = 0.0f;
#pragma unroll
    for (int g = 0; g < HEADS; g++) {
        float e = __expf(sc[g] - mx);
        sc[g] = e;
        sum += e;
    }
    const float inv = 1.0f / sum;

    float acc[HD];
#pragma unroll
    for (int d = 0; d < HD; d++) acc[d] = 0.0f;
#pragma unroll
    for (int g = 0; g < HEADS; g++) {
        const float p = sc[g];
#pragma unroll
        for (int d = 0; d < HD; d++) acc[d] += p * vs[t][g][d];
    }

    float* orow = out + row * DIM + h * HD;
#pragma unroll
    for (int d = 0; d < HD; d += 4) {
        float4 o;
        o.x = acc[d]   * inv; o.y = acc[d+1] * inv;
        o.z = acc[d+2] * inv; o.w = acc[d+3] * inv;
        *(float4*)(orow + d) = o;
    }
}

// ===================== Launch ===============================================
extern "C" void kernel_launch(void* const* d_in, const int* in_sizes, int n_in,
                              void* d_out, int out_size)
{
    const float* x      = (const float*)d_in[0];
    const float* ln1_g  = (const float*)d_in[1];
    const float* ln1_b  = (const float*)d_in[2];
    const float* qkv_w  = (const float*)d_in[3];
    const float* qkv_b  = (const float*)d_in[4];
    const float* proj_w = (const float*)d_in[5];
    const float* proj_b = (const float*)d_in[6];
    const float* ln2_g  = (const float*)d_in[7];
    const float* ln2_b  = (const float*)d_in[8];
    const float* ffn_w1 = (const float*)d_in[9];
    const float* ffn_b1 = (const float*)d_in[10];
    const float* ffn_w2 = (const float*)d_in[11];
    const float* ffn_b2 = (const float*)d_in[12];

    float *xn, *qkv, *attn, *y, *h;
    cudaGetSymbolAddress((void**)&xn,   g_xn);
    cudaGetSymbolAddress((void**)&qkv,  g_qkv);
    cudaGetSymbolAddress((void**)&attn, g_attn);
    cudaGetSymbolAddress((void**)&y,    g_y);
    cudaGetSymbolAddress((void**)&h,    g_h);
    float* out = (float*)d_out;

    cudaFuncSetAttribute(mma_gemm<0>, cudaFuncAttributeMaxDynamicSharedMemorySize, GEMM_SMEM);
    cudaFuncSetAttribute(mma_gemm<1>, cudaFuncAttributeMaxDynamicSharedMemorySize, GEMM_SMEM);
    cudaFuncSetAttribute(mma_gemm<2>, cudaFuncAttributeMaxDynamicSharedMemorySize, GEMM_SMEM);

    const int MROWS = TOKENS / TILE;   // 512

    // 1) LN1
    ln_kernel<<<TOKENS / 8, 256>>>(x, ln1_g, ln1_b, xn);
    // 2) QKV = xn @ qkv_w^T + qkv_b          [65536, 768]
    mma_gemm<0><<<dim3(768 / TILE, MROWS), 256, GEMM_SMEM>>>(
        xn, qkv_w, qkv_b, nullptr, qkv, DIM, 3 * DIM);
    // 3) per-token head-mixing attention     [65536, 256]
    attn_kernel<<<TOKENS / 16, 128>>>(qkv, attn);
    // 4) y = x + attn @ proj_w^T + proj_b
    mma_gemm<2><<<dim3(DIM / TILE, MROWS), 256, GEMM_SMEM>>>(
        attn, proj_w, proj_b, x, y, DIM, DIM);
    // 5) LN2
    ln_kernel<<<TOKENS / 8, 256>>>(y, ln2_g, ln2_b, xn);
    // 6) h = relu(xn @ ffn_w1^T + ffn_b1)    [65536, 1024]
    mma_gemm<1><<<dim3(FFNDIM / TILE, MROWS), 256, GEMM_SMEM>>>(
        xn, ffn_w1, ffn_b1, nullptr, h, DIM, FFNDIM);
    // 7) out = y + h @ ffn_w2^T + ffn_b2
    mma_gemm<2><<<dim3(DIM / TILE, MROWS), 256, GEMM_SMEM>>>(
        h, ffn_w2, ffn_b2, y, out, FFNDIM, DIM);
}

// round 5
// speedup vs baseline: 3.3210x; 1.2142x over previous
#include <cuda_runtime.h>
#include <cstdint>
#include <cstring>

// ---------------------------------------------------------------------------
// SimpleMaxViTBlock: LN1 -> per-token head-mixing attention -> +res
//                    -> LN2 -> FFN -> +res
// GEMMs: legacy mma.sync m16n8k8 tf32. All GEMM operands are pre-rounded to
// tf32 by the producers (LN / attn / FFN1-epilogue / weight-round kernel), so
// the GEMM inner loop is pure LDS + MMA.
// ---------------------------------------------------------------------------

constexpr int TOKENS = 65536;
constexpr int DIM    = 256;
constexpr int HEADS  = 8;
constexpr int HD     = 32;
constexpr int FFNDIM = 1024;

// Scratch (device globals: allocation-free rule)
__device__ float g_xn  [ (size_t)TOKENS * DIM    ];
__device__ float g_qkv [ (size_t)TOKENS * 3*DIM  ];
__device__ float g_attn[ (size_t)TOKENS * DIM    ];
__device__ float g_y   [ (size_t)TOKENS * DIM    ];
__device__ float g_h   [ (size_t)TOKENS * FFNDIM ];
__device__ float g_w   [ 786432 ];   // tf32-rounded weights

constexpr int W_QKV  = 0;
constexpr int W_PROJ = 196608;
constexpr int W_FFN1 = 262144;
constexpr int W_FFN2 = 524288;

// ===================== helpers ==============================================
__device__ __forceinline__ uint32_t smem_u32(const void* p) {
    uint32_t a;
    asm("{ .reg .u64 t; cvta.to.shared.u64 t, %1; cvt.u32.u64 %0, t; }"
        : "=r"(a) : "l"(p));
    return a;
}
__device__ __forceinline__ float f2tf32f(float x) {
    uint32_t r;
    asm("cvt.rna.tf32.f32 %0, %1;" : "=r"(r) : "f"(x));
    return __uint_as_float(r);
}
__device__ __forceinline__ void cp_async16(uint32_t saddr, const void* gaddr) {
    asm volatile("cp.async.cg.shared.global [%0], [%1], 16;"
                 :: "r"(saddr), "l"(gaddr) : "memory");
}
__device__ __forceinline__ void cp_commit() {
    asm volatile("cp.async.commit_group;" ::: "memory");
}
template<int N>
__device__ __forceinline__ void cp_wait() {
    asm volatile("cp.async.wait_group %0;" :: "n"(N) : "memory");
}
__device__ __forceinline__ void mma_tf32(
    float& d0, float& d1, float& d2, float& d3,
    uint32_t a0, uint32_t a1, uint32_t a2, uint32_t a3,
    uint32_t b0, uint32_t b1)
{
    asm volatile(
        "mma.sync.aligned.m16n8k8.row.col.f32.tf32.tf32.f32 "
        "{%0,%1,%2,%3}, {%4,%5,%6,%7}, {%8,%9}, {%0,%1,%2,%3};"
        : "+f"(d0), "+f"(d1), "+f"(d2), "+f"(d3)
        : "r"(a0), "r"(a1), "r"(a2), "r"(a3), "r"(b0), "r"(b1));
}

// ===================== tf32 mma.sync GEMM ===================================
// C[m,n] = epi( sum_k A[m,k]*B[n,k] + bias[n] [+res] ), A:[M,K], B:[N,K] rowmaj
// A,B already tf32-rounded. CTA 128x128, BK=32, double-buffered cp.async,
// 8 warps (4M x 2N), warp 32x64, fragments double-buffered across k-steps.
// MODE: 0=bias, 1=bias+relu (+round to tf32), 2=bias+residual
constexpr int TILE   = 128;
constexpr int BK     = 32;
constexpr int LDP    = 36;
constexpr int SLAB   = TILE * LDP;
constexpr int GEMM_SMEM = 2 * 2 * SLAB * 4;      // 73728 B

template<int MODE>
__global__ void __launch_bounds__(256) mma_gemm(
    const float* __restrict__ A, const float* __restrict__ B,
    const float* __restrict__ bias, const float* __restrict__ res,
    float* __restrict__ C, int K, int N)
{
    extern __shared__ float sm[];
    float* As = sm;                 // [2][128][36]
    float* Bs = sm + 2 * SLAB;      // [2][128][36]
    const uint32_t As_u = smem_u32(As);
    const uint32_t Bs_u = smem_u32(Bs);

    const int tid  = threadIdx.x;
    const int wid  = tid >> 5;
    const int lane = tid & 31;
    const int gid  = lane >> 2;     // 0..7
    const int tg   = lane & 3;      // 0..3

    const int bm = blockIdx.y * TILE;
    const int bn = blockIdx.x * TILE;
    const int m_off = (wid >> 1) * 32;
    const int n_off = (wid & 1) * 64;

    const int crow = tid >> 3;
    const int cc4  = (tid & 7) * 4;

    float d[2][8][4];
#pragma unroll
    for (int mt = 0; mt < 2; mt++)
#pragma unroll
        for (int nt = 0; nt < 8; nt++)
#pragma unroll
            for (int j = 0; j < 4; j++) d[mt][nt][j] = 0.0f;

    const int C_CHUNKS = K / BK;

    // stage 0
    {
#pragma unroll
        for (int it = 0; it < 4; it++) {
            int row = crow + it * 32;
            cp_async16(As_u + (uint32_t)(row * LDP + cc4) * 4,
                       A + (size_t)(bm + row) * K + cc4);
            cp_async16(Bs_u + (uint32_t)(row * LDP + cc4) * 4,
                       B + (size_t)(bn + row) * K + cc4);
        }
        cp_commit();
    }

    for (int c = 0; c < C_CHUNKS; c++) {
        const int buf = c & 1;
        if (c + 1 < C_CHUNKS) {
            const int nb = (c + 1) & 1;
            const int k0g = (c + 1) * BK;
#pragma unroll
            for (int it = 0; it < 4; it++) {
                int row = crow + it * 32;
                cp_async16(As_u + (uint32_t)((nb * SLAB + row * LDP + cc4) * 4),
                           A + (size_t)(bm + row) * K + k0g + cc4);
                cp_async16(Bs_u + (uint32_t)((nb * SLAB + row * LDP + cc4) * 4),
                           B + (size_t)(bn + row) * K + k0g + cc4);
            }
            cp_commit();
            cp_wait<1>();
        } else {
            cp_wait<0>();
        }
        __syncthreads();

        const uint32_t* Ab = (const uint32_t*)(As + buf * SLAB);
        const uint32_t* Bb = (const uint32_t*)(Bs + buf * SLAB);

        // fragment double-buffer across 4 k-steps
        uint32_t a[2][2][4], b[2][8][2];

#pragma unroll
        for (int mt = 0; mt < 2; mt++) {
            const int r0 = m_off + mt * 16 + gid;
            a[0][mt][0] = Ab[(r0)     * LDP + tg];
            a[0][mt][1] = Ab[(r0 + 8) * LDP + tg];
            a[0][mt][2] = Ab[(r0)     * LDP + tg + 4];
            a[0][mt][3] = Ab[(r0 + 8) * LDP + tg + 4];
        }
#pragma unroll
        for (int nt = 0; nt < 8; nt++) {
            const int c0 = n_off + nt * 8 + gid;
            b[0][nt][0] = Bb[c0 * LDP + tg];
            b[0][nt][1] = Bb[c0 * LDP + tg + 4];
        }

#pragma unroll
        for (int ks = 0; ks < 4; ks++) {
            const int cur = ks & 1;
            const int nxt = cur ^ 1;
            if (ks < 3) {
                const int k0 = (ks + 1) * 8;
#pragma unroll
                for (int mt = 0; mt < 2; mt++) {
                    const int r0 = m_off + mt * 16 + gid;
                    a[nxt][mt][0] = Ab[(r0)     * LDP + k0 + tg];
                    a[nxt][mt][1] = Ab[(r0 + 8) * LDP + k0 + tg];
                    a[nxt][mt][2] = Ab[(r0)     * LDP + k0 + tg + 4];
                    a[nxt][mt][3] = Ab[(r0 + 8) * LDP + k0 + tg + 4];
                }
#pragma unroll
                for (int nt = 0; nt < 8; nt++) {
                    const int c0 = n_off + nt * 8 + gid;
                    b[nxt][nt][0] = Bb[c0 * LDP + k0 + tg];
                    b[nxt][nt][1] = Bb[c0 * LDP + k0 + tg + 4];
                }
            }
#pragma unroll
            for (int mt = 0; mt < 2; mt++)
#pragma unroll
                for (int nt = 0; nt < 8; nt++)
                    mma_tf32(d[mt][nt][0], d[mt][nt][1], d[mt][nt][2], d[mt][nt][3],
                             a[cur][mt][0], a[cur][mt][1], a[cur][mt][2], a[cur][mt][3],
                             b[cur][nt][0], b[cur][nt][1]);
        }
        __syncthreads();
    }

    // ---- epilogue ----
#pragma unroll
    for (int nt = 0; nt < 8; nt++) {
        const int n = bn + n_off + nt * 8 + 2 * tg;
        const float2 bv = *(const float2*)&bias[n];
#pragma unroll
        for (int mt = 0; mt < 2; mt++) {
            const int m0 = bm + m_off + mt * 16 + gid;
#pragma unroll
            for (int half = 0; half < 2; half++) {
                const int m = m0 + half * 8;
                float2 v;
                v.x = d[mt][nt][half * 2 + 0] + bv.x;
                v.y = d[mt][nt][half * 2 + 1] + bv.y;
                if (MODE == 1) {
                    v.x = f2tf32f(fmaxf(v.x, 0.f));
                    v.y = f2tf32f(fmaxf(v.y, 0.f));
                }
                if (MODE == 2) {
                    const float2 r = *(const float2*)&res[(size_t)m * N + n];
                    v.x += r.x; v.y += r.y;
                }
                *(float2*)&C[(size_t)m * N + n] = v;
            }
        }
    }
}

// ===================== weight rounding ======================================
__global__ void __launch_bounds__(256) round_w(
    const float* __restrict__ src, float* __restrict__ dst, int n4)
{
    int i = blockIdx.x * 256 + threadIdx.x;
    if (i < n4) {
        float4 v = ((const float4*)src)[i];
        v.x = f2tf32f(v.x); v.y = f2tf32f(v.y);
        v.z = f2tf32f(v.z); v.w = f2tf32f(v.w);
        ((float4*)dst)[i] = v;
    }
}

// ===================== LayerNorm (one warp per 256-float row) ===============
// Output rounded to tf32 (feeds GEMM A operand only).
__global__ void __launch_bounds__(256) ln_kernel(
    const float* __restrict__ x, const float* __restrict__ g,
    const float* __restrict__ b, float* __restrict__ out)
{
    int row  = (blockIdx.x * blockDim.x + threadIdx.x) >> 5;
    int lane = threadIdx.x & 31;
    const float4* xr = (const float4*)(x + (size_t)row * DIM);
    float4 v0 = xr[lane];
    float4 v1 = xr[lane + 32];

    float s = v0.x + v0.y + v0.z + v0.w + v1.x + v1.y + v1.z + v1.w;
    float q = v0.x*v0.x + v0.y*v0.y + v0.z*v0.z + v0.w*v0.w
            + v1.x*v1.x + v1.y*v1.y + v1.z*v1.z + v1.w*v1.w;
#pragma unroll
    for (int o = 16; o > 0; o >>= 1) {
        s += __shfl_xor_sync(0xffffffffu, s, o);
        q += __shfl_xor_sync(0xffffffffu, q, o);
    }
    float mean = s * (1.0f / 256.0f);
    float var  = q * (1.0f / 256.0f) - mean * mean;
    float inv  = rsqrtf(var + 1e-5f);

    const float4* g4 = (const float4*)g;
    const float4* b4 = (const float4*)b;
    float4 ga = g4[lane], gb = g4[lane + 32];
    float4 ba = b4[lane], bb = b4[lane + 32];

    float4 o0, o1;
    o0.x = f2tf32f((v0.x - mean) * inv * ga.x + ba.x);
    o0.y = f2tf32f((v0.y - mean) * inv * ga.y + ba.y);
    o0.z = f2tf32f((v0.z - mean) * inv * ga.z + ba.z);
    o0.w = f2tf32f((v0.w - mean) * inv * ga.w + ba.w);
    o1.x = f2tf32f((v1.x - mean) * inv * gb.x + bb.x);
    o1.y = f2tf32f((v1.y - mean) * inv * gb.y + bb.y);
    o1.z = f2tf32f((v1.z - mean) * inv * gb.z + bb.z);
    o1.w = f2tf32f((v1.w - mean) * inv * gb.w + bb.w);

    float4* orow = (float4*)(out + (size_t)row * DIM);
    orow[lane]      = o0;
    orow[lane + 32] = o1;
}

// ===================== Per-token head-mixing attention ======================
// Output rounded to tf32 (feeds proj GEMM A operand only).
__global__ void __launch_bounds__(128) attn_kernel(
    const float* __restrict__ qkv, float* __restrict__ out)
{
    __shared__ __align__(16) float ks[16][HEADS][HD + 1];
    __shared__ __align__(16) float vs[16][HEADS][HD + 1];

    const int tok0 = blockIdx.x * 16;
    const int tid  = threadIdx.x;

#pragma unroll
    for (int it = 0; it < 8; it++) {
        int fi  = tid + it * 128;
        int t   = fi >> 6;
        int q4  = fi & 63;
        int g   = q4 >> 3;
        int d   = (q4 & 7) * 4;
        const float* base = qkv + (size_t)(tok0 + t) * 768;
        float4 kv = *(const float4*)(base + 256 + g * HD + d);
        float4 vv = *(const float4*)(base + 512 + g * HD + d);
        ks[t][g][d] = kv.x; ks[t][g][d+1] = kv.y;
        ks[t][g][d+2] = kv.z; ks[t][g][d+3] = kv.w;
        vs[t][g][d] = vv.x; vs[t][g][d+1] = vv.y;
        vs[t][g][d+2] = vv.z; vs[t][g][d+3] = vv.w;
    }
    __syncthreads();

    const int t = tid >> 3;
    const int h = tid & 7;
    const size_t row = (size_t)(tok0 + t);

    float q[HD];
    const float* qrow = qkv + row * 768 + h * HD;
#pragma unroll
    for (int d = 0; d < HD; d += 4) {
        float4 qv = *(const float4*)(qrow + d);
        q[d] = qv.x; q[d+1] = qv.y; q[d+2] = qv.z; q[d+3] = qv.w;
    }

    const float scale = 0.17677669529663688f;   // 1/sqrt(32)
    float sc[HEADS];
    float mx = -1e30f;
#pragma unroll
    for (int g = 0; g < HEADS; g++) {
        float s = 0.0f;
#pragma unroll
        for (int d = 0; d < HD; d++) s += q[d] * ks[t][g][d];
        s *= scale;
        sc[g] = s;
        mx = fmaxf(mx, s);
    }
    float sum = 0.0f;
#pragma unroll
    for (int g = 0; g < HEADS; g++) {
        float e = __expf(sc[g] - mx);
        sc[g] = e;
        sum += e;
    }
    const float inv = 1.0f / sum;

    float acc[HD];
#pragma unroll
    for (int d = 0; d < HD; d++) acc[d] = 0.0f;
#pragma unroll
    for (int g = 0; g < HEADS; g++) {
        const float p = sc[g];
#pragma unroll
        for (int d = 0; d < HD; d++) acc[d] += p * vs[t][g][d];
    }

    float* orow = out + row * DIM + h * HD;
#pragma unroll
    for (int d = 0; d < HD; d += 4) {
        float4 o;
        o.x = f2tf32f(acc[d]   * inv); o.y = f2tf32f(acc[d+1] * inv);
        o.z = f2tf32f(acc[d+2] * inv); o.w = f2tf32f(acc[d+3] * inv);
        *(float4*)(orow + d) = o;
    }
}

// ===================== Launch ===============================================
extern "C" void kernel_launch(void* const* d_in, const int* in_sizes, int n_in,
                              void* d_out, int out_size)
{
    const float* x      = (const float*)d_in[0];
    const float* ln1_g  = (const float*)d_in[1];
    const float* ln1_b  = (const float*)d_in[2];
    const float* qkv_w  = (const float*)d_in[3];
    const float* qkv_b  = (const float*)d_in[4];
    const float* proj_w = (const float*)d_in[5];
    const float* proj_b = (const float*)d_in[6];
    const float* ln2_g  = (const float*)d_in[7];
    const float* ln2_b  = (const float*)d_in[8];
    const float* ffn_w1 = (const float*)d_in[9];
    const float* ffn_b1 = (const float*)d_in[10];
    const float* ffn_w2 = (const float*)d_in[11];
    const float* ffn_b2 = (const float*)d_in[12];

    float *xn, *qkv, *attn, *y, *h, *w;
    cudaGetSymbolAddress((void**)&xn,   g_xn);
    cudaGetSymbolAddress((void**)&qkv,  g_qkv);
    cudaGetSymbolAddress((void**)&attn, g_attn);
    cudaGetSymbolAddress((void**)&y,    g_y);
    cudaGetSymbolAddress((void**)&h,    g_h);
    cudaGetSymbolAddress((void**)&w,    g_w);
    float* out = (float*)d_out;

    cudaFuncSetAttribute(mma_gemm<0>, cudaFuncAttributeMaxDynamicSharedMemorySize, GEMM_SMEM);
    cudaFuncSetAttribute(mma_gemm<1>, cudaFuncAttributeMaxDynamicSharedMemorySize, GEMM_SMEM);
    cudaFuncSetAttribute(mma_gemm<2>, cudaFuncAttributeMaxDynamicSharedMemorySize, GEMM_SMEM);

    const int MROWS = TOKENS / TILE;   // 512

    // 0) round weights to tf32 once per launch (constant inputs -> deterministic)
    round_w<<<(196608/4 + 255)/256, 256>>>(qkv_w,  w + W_QKV,  196608/4);
    round_w<<<( 65536/4 + 255)/256, 256>>>(proj_w, w + W_PROJ,  65536/4);
    round_w<<<(262144/4 + 255)/256, 256>>>(ffn_w1, w + W_FFN1, 262144/4);
    round_w<<<(262144/4 + 255)/256, 256>>>(ffn_w2, w + W_FFN2, 262144/4);

    // 1) LN1 (tf32-rounded output)
    ln_kernel<<<TOKENS / 8, 256>>>(x, ln1_g, ln1_b, xn);
    // 2) QKV = xn @ qkv_w^T + qkv_b          [65536, 768]
    mma_gemm<0><<<dim3(768 / TILE, MROWS), 256, GEMM_SMEM>>>(
        xn, w + W_QKV, qkv_b, nullptr, qkv, DIM, 3 * DIM);
    // 3) per-token head-mixing attention (tf32-rounded output)
    attn_kernel<<<TOKENS / 16, 128>>>(qkv, attn);
    // 4) y = x + attn @ proj_w^T + proj_b
    mma_gemm<2><<<dim3(DIM / TILE, MROWS), 256, GEMM_SMEM>>>(
        attn, w + W_PROJ, proj_b, x, y, DIM, DIM);
    // 5) LN2 (tf32-rounded output)
    ln_kernel<<<TOKENS / 8, 256>>>(y, ln2_g, ln2_b, xn);
    // 6) h = relu(xn @ ffn_w1^T + ffn_b1), rounded   [65536, 1024]
    mma_gemm<1><<<dim3(FFNDIM / TILE, MROWS), 256, GEMM_SMEM>>>(
        xn, w + W_FFN1, ffn_b1, nullptr, h, DIM, FFNDIM);
    // 7) out = y + h @ ffn_w2^T + ffn_b2
    mma_gemm<2><<<dim3(DIM / TILE, MROWS), 256, GEMM_SMEM>>>(
        h, w + W_FFN2, ffn_b2, y, out, FFNDIM, DIM);
}

// round 6
// speedup vs baseline: 5.0868x; 1.5317x over previous
#include <cuda_runtime.h>
#include <cuda_fp16.h>
#include <cstdint>

// ---------------------------------------------------------------------------
// SimpleMaxViTBlock: LN1 -> per-token head-mixing attention -> +res
//                    -> LN2 -> FFN -> +res
// GEMMs: mma.sync m16n8k16 fp16 (same 10-bit mantissa as tf32, fp32 accum).
// Producers emit __half; residuals/bias stay fp32.
// ---------------------------------------------------------------------------

constexpr int TOKENS = 65536;
constexpr int DIM    = 256;
constexpr int HEADS  = 8;
constexpr int HD     = 32;
constexpr int FFNDIM = 1024;

// Scratch (device globals: allocation-free rule)
__device__ __half g_xn  [ (size_t)TOKENS * DIM    ];
__device__ __half g_qkv [ (size_t)TOKENS * 3*DIM  ];
__device__ __half g_attn[ (size_t)TOKENS * DIM    ];
__device__ float  g_y   [ (size_t)TOKENS * DIM    ];
__device__ __half g_h   [ (size_t)TOKENS * FFNDIM ];
__device__ __half g_w   [ 786432 ];   // fp16-rounded weights

constexpr int W_QKV  = 0;
constexpr int W_PROJ = 196608;
constexpr int W_FFN1 = 262144;
constexpr int W_FFN2 = 524288;

// ===================== helpers ==============================================
__device__ __forceinline__ uint32_t smem_u32(const void* p) {
    uint32_t a;
    asm("{ .reg .u64 t; cvta.to.shared.u64 t, %1; cvt.u32.u64 %0, t; }"
        : "=r"(a) : "l"(p));
    return a;
}
__device__ __forceinline__ void cp_async16(uint32_t saddr, const void* gaddr) {
    asm volatile("cp.async.cg.shared.global [%0], [%1], 16;"
                 :: "r"(saddr), "l"(gaddr) : "memory");
}
__device__ __forceinline__ void cp_commit() {
    asm volatile("cp.async.commit_group;" ::: "memory");
}
template<int N>
__device__ __forceinline__ void cp_wait() {
    asm volatile("cp.async.wait_group %0;" :: "n"(N) : "memory");
}
__device__ __forceinline__ void mma_f16(
    float& d0, float& d1, float& d2, float& d3,
    uint32_t a0, uint32_t a1, uint32_t a2, uint32_t a3,
    uint32_t b0, uint32_t b1)
{
    asm volatile(
        "mma.sync.aligned.m16n8k16.row.col.f32.f16.f16.f32 "
        "{%0,%1,%2,%3}, {%4,%5,%6,%7}, {%8,%9}, {%0,%1,%2,%3};"
        : "+f"(d0), "+f"(d1), "+f"(d2), "+f"(d3)
        : "r"(a0), "r"(a1), "r"(a2), "r"(a3), "r"(b0), "r"(b1));
}

// ===================== fp16 mma.sync GEMM ===================================
// C[m,n] = epi( sum_k A[m,k]*B[n,k] + bias[n] [+res] )
// A:[M,K], B:[N,K] row-major __half. CTA 128x128, BK=32 (halves),
// double-buffered cp.async, 8 warps (4M x 2N), warp 32x64.
// Row stride in smem: 40 halves = 20 u32 (conflict-free fragment loads).
// MODE: 0 = bias -> half out, 1 = bias+relu -> half out, 2 = bias+res -> f32
constexpr int TILE  = 128;
constexpr int BK    = 32;
constexpr int LDU   = 20;              // u32 per smem row (= 40 halves)
constexpr int SLABU = TILE * LDU;      // 2560 u32 per stage per matrix

template<int MODE, typename OutT>
__global__ void __launch_bounds__(256) mma_gemm(
    const __half* __restrict__ A, const __half* __restrict__ B,
    const float* __restrict__ bias, const float* __restrict__ res,
    OutT* __restrict__ C, int K, int N)
{
    __shared__ __align__(16) uint32_t sm[4 * SLABU];   // 40960 B
    uint32_t* As = sm;                  // [2][128][20]
    uint32_t* Bs = sm + 2 * SLABU;
    const uint32_t As_u = smem_u32(As);
    const uint32_t Bs_u = smem_u32(Bs);

    const int tid  = threadIdx.x;
    const int wid  = tid >> 5;
    const int lane = tid & 31;
    const int gid  = lane >> 2;     // 0..7
    const int tg   = lane & 3;      // 0..3

    const int bm = blockIdx.y * TILE;
    const int bn = blockIdx.x * TILE;
    const int m_off = (wid >> 1) * 32;
    const int n_off = (wid & 1) * 64;

    // cp.async mapping: fi = tid + it*256 over 512 16B-transfers per matrix
    const int crow = tid >> 2;          // +64 per it
    const int cc8  = (tid & 3) * 8;     // half offset within 32-half row

    float d[2][8][4];
#pragma unroll
    for (int mt = 0; mt < 2; mt++)
#pragma unroll
        for (int nt = 0; nt < 8; nt++)
#pragma unroll
            for (int j = 0; j < 4; j++) d[mt][nt][j] = 0.0f;

    const int C_CHUNKS = K / BK;

    // stage 0
    {
#pragma unroll
        for (int it = 0; it < 2; it++) {
            int row = crow + it * 64;
            cp_async16(As_u + (uint32_t)(row * LDU + cc8 / 2) * 4,
                       A + (size_t)(bm + row) * K + cc8);
            cp_async16(Bs_u + (uint32_t)(row * LDU + cc8 / 2) * 4,
                       B + (size_t)(bn + row) * K + cc8);
        }
        cp_commit();
    }

    for (int c = 0; c < C_CHUNKS; c++) {
        const int buf = c & 1;
        if (c + 1 < C_CHUNKS) {
            const int nb  = (c + 1) & 1;
            const int k0g = (c + 1) * BK;
#pragma unroll
            for (int it = 0; it < 2; it++) {
                int row = crow + it * 64;
                cp_async16(As_u + (uint32_t)((nb * SLABU + row * LDU + cc8 / 2) * 4),
                           A + (size_t)(bm + row) * K + k0g + cc8);
                cp_async16(Bs_u + (uint32_t)((nb * SLABU + row * LDU + cc8 / 2) * 4),
                           B + (size_t)(bn + row) * K + k0g + cc8);
            }
            cp_commit();
            cp_wait<1>();
        } else {
            cp_wait<0>();
        }
        __syncthreads();

        const uint32_t* Ab = As + buf * SLABU;
        const uint32_t* Bb = Bs + buf * SLABU;

        // 2 k-steps of 16; fragments double-buffered across steps
        uint32_t a[2][2][4], b[2][8][2];

#pragma unroll
        for (int mt = 0; mt < 2; mt++) {
            const int r0 = m_off + mt * 16 + gid;
            a[0][mt][0] = Ab[(r0)     * LDU + tg];
            a[0][mt][1] = Ab[(r0 + 8) * LDU + tg];
            a[0][mt][2] = Ab[(r0)     * LDU + tg + 4];
            a[0][mt][3] = Ab[(r0 + 8) * LDU + tg + 4];
        }
#pragma unroll
        for (int nt = 0; nt < 8; nt++) {
            const int c0 = n_off + nt * 8 + gid;
            b[0][nt][0] = Bb[c0 * LDU + tg];
            b[0][nt][1] = Bb[c0 * LDU + tg + 4];
        }

#pragma unroll
        for (int ks = 0; ks < 2; ks++) {
            const int cur = ks & 1;
            const int nxt = cur ^ 1;
            if (ks < 1) {
                const int ko = 8;   // 16 halves
#pragma unroll
                for (int mt = 0; mt < 2; mt++) {
                    const int r0 = m_off + mt * 16 + gid;
                    a[nxt][mt][0] = Ab[(r0)     * LDU + ko + tg];
                    a[nxt][mt][1] = Ab[(r0 + 8) * LDU + ko + tg];
                    a[nxt][mt][2] = Ab[(r0)     * LDU + ko + tg + 4];
                    a[nxt][mt][3] = Ab[(r0 + 8) * LDU + ko + tg + 4];
                }
#pragma unroll
                for (int nt = 0; nt < 8; nt++) {
                    const int c0 = n_off + nt * 8 + gid;
                    b[nxt][nt][0] = Bb[c0 * LDU + ko + tg];
                    b[nxt][nt][1] = Bb[c0 * LDU + ko + tg + 4];
                }
            }
#pragma unroll
            for (int mt = 0; mt < 2; mt++)
#pragma unroll
                for (int nt = 0; nt < 8; nt++)
                    mma_f16(d[mt][nt][0], d[mt][nt][1], d[mt][nt][2], d[mt][nt][3],
                            a[cur][mt][0], a[cur][mt][1], a[cur][mt][2], a[cur][mt][3],
                            b[cur][nt][0], b[cur][nt][1]);
        }
        __syncthreads();
    }

    // ---- epilogue ----
#pragma unroll
    for (int nt = 0; nt < 8; nt++) {
        const int n = bn + n_off + nt * 8 + 2 * tg;
        const float2 bv = *(const float2*)&bias[n];
#pragma unroll
        for (int mt = 0; mt < 2; mt++) {
            const int m0 = bm + m_off + mt * 16 + gid;
#pragma unroll
            for (int half_i = 0; half_i < 2; half_i++) {
                const int m = m0 + half_i * 8;
                float vx = d[mt][nt][half_i * 2 + 0] + bv.x;
                float vy = d[mt][nt][half_i * 2 + 1] + bv.y;
                if (MODE == 1) { vx = fmaxf(vx, 0.f); vy = fmaxf(vy, 0.f); }
                if (MODE == 2) {
                    const float2 r = *(const float2*)&res[(size_t)m * N + n];
                    float2 v; v.x = vx + r.x; v.y = vy + r.y;
                    *(float2*)&((float*)C)[(size_t)m * N + n] = v;
                } else {
                    *(__half2*)&((__half*)C)[(size_t)m * N + n] =
                        __floats2half2_rn(vx, vy);
                }
            }
        }
    }
}

// ===================== weight rounding (f32 -> f16) =========================
__global__ void __launch_bounds__(256) round_w(
    const float* __restrict__ src, __half* __restrict__ dst, int n4)
{
    int i = blockIdx.x * 256 + threadIdx.x;
    if (i < n4) {
        float4 v = ((const float4*)src)[i];
        __half2 lo = __floats2half2_rn(v.x, v.y);
        __half2 hi = __floats2half2_rn(v.z, v.w);
        uint2 o; o.x = *(uint32_t*)&lo; o.y = *(uint32_t*)&hi;
        ((uint2*)dst)[i] = o;
    }
}

// ===================== LayerNorm (one warp per 256-float row) ===============
// fp32 in, __half out (feeds GEMM A operand only).
__global__ void __launch_bounds__(256) ln_kernel(
    const float* __restrict__ x, const float* __restrict__ g,
    const float* __restrict__ b, __half* __restrict__ out)
{
    int row  = (blockIdx.x * blockDim.x + threadIdx.x) >> 5;
    int lane = threadIdx.x & 31;
    const float4* xr = (const float4*)(x + (size_t)row * DIM);
    float4 v0 = xr[lane];
    float4 v1 = xr[lane + 32];

    float s = v0.x + v0.y + v0.z + v0.w + v1.x + v1.y + v1.z + v1.w;
    float q = v0.x*v0.x + v0.y*v0.y + v0.z*v0.z + v0.w*v0.w
            + v1.x*v1.x + v1.y*v1.y + v1.z*v1.z + v1.w*v1.w;
#pragma unroll
    for (int o = 16; o > 0; o >>= 1) {
        s += __shfl_xor_sync(0xffffffffu, s, o);
        q += __shfl_xor_sync(0xffffffffu, q, o);
    }
    float mean = s * (1.0f / 256.0f);
    float var  = q * (1.0f / 256.0f) - mean * mean;
    float inv  = rsqrtf(var + 1e-5f);

    const float4* g4 = (const float4*)g;
    const float4* b4 = (const float4*)b;
    float4 ga = g4[lane], gb = g4[lane + 32];
    float4 ba = b4[lane], bb = b4[lane + 32];

    __half2 h0 = __floats2half2_rn((v0.x - mean) * inv * ga.x + ba.x,
                                   (v0.y - mean) * inv * ga.y + ba.y);
    __half2 h1 = __floats2half2_rn((v0.z - mean) * inv * ga.z + ba.z,
                                   (v0.w - mean) * inv * ga.w + ba.w);
    __half2 h2 = __floats2half2_rn((v1.x - mean) * inv * gb.x + bb.x,
                                   (v1.y - mean) * inv * gb.y + bb.y);
    __half2 h3 = __floats2half2_rn((v1.z - mean) * inv * gb.z + bb.z,
                                   (v1.w - mean) * inv * gb.w + bb.w);

    __half* orow = out + (size_t)row * DIM;
    uint2 p0; p0.x = *(uint32_t*)&h0; p0.y = *(uint32_t*)&h1;
    uint2 p1; p1.x = *(uint32_t*)&h2; p1.y = *(uint32_t*)&h3;
    *(uint2*)(orow + lane * 4)       = p0;
    *(uint2*)(orow + 128 + lane * 4) = p1;
}

// ===================== Per-token head-mixing attention ======================
// __half qkv in, __half out. Math in fp32.
__global__ void __launch_bounds__(128) attn_kernel(
    const __half* __restrict__ qkv, __half* __restrict__ out)
{
    __shared__ __align__(16) float ks[16][HEADS][HD + 1];
    __shared__ __align__(16) float vs[16][HEADS][HD + 1];

    const int tok0 = blockIdx.x * 16;
    const int tid  = threadIdx.x;

    // cooperative K/V staging: 16 tokens x 256 halves each region,
    // 512 x 16B loads per region, 128 threads x 4 iters
#pragma unroll
    for (int it = 0; it < 4; it++) {
        int fi = tid + it * 128;            // 0..511
        int t  = fi >> 5;                   // token
        int c  = fi & 31;                   // 16B chunk within 256 halves
        int g  = c >> 2;                    // head
        int d  = (c & 3) * 8;               // dim
        const __half* base = qkv + (size_t)(tok0 + t) * 768;
        uint4 kv = *(const uint4*)(base + 256 + g * HD + d);
        uint4 vv = *(const uint4*)(base + 512 + g * HD + d);
        const __half2* kh = (const __half2*)&kv;
        const __half2* vh = (const __half2*)&vv;
#pragma unroll
        for (int j = 0; j < 4; j++) {
            float2 kf = __half22float2(kh[j]);
            float2 vf = __half22float2(vh[j]);
            ks[t][g][d + 2*j]     = kf.x;
            ks[t][g][d + 2*j + 1] = kf.y;
            vs[t][g][d + 2*j]     = vf.x;
            vs[t][g][d + 2*j + 1] = vf.y;
        }
    }
    __syncthreads();

    const int t = tid >> 3;
    const int h = tid & 7;
    const size_t row = (size_t)(tok0 + t);

    float q[HD];
    {
        const __half* qrow = qkv + row * 768 + h * HD;
#pragma unroll
        for (int c = 0; c < 4; c++) {
            uint4 qv = *(const uint4*)(qrow + c * 8);
            const __half2* qh = (const __half2*)&qv;
#pragma unroll
            for (int j = 0; j < 4; j++) {
                float2 qf = __half22float2(qh[j]);
                q[c * 8 + 2*j]     = qf.x;
                q[c * 8 + 2*j + 1] = qf.y;
            }
        }
    }

    const float scale = 0.17677669529663688f;   // 1/sqrt(32)
    float sc[HEADS];
    float mx = -1e30f;
#pragma unroll
    for (int g = 0; g < HEADS; g++) {
        float s = 0.0f;
#pragma unroll
        for (int d = 0; d < HD; d++) s += q[d] * ks[t][g][d];
        s *= scale;
        sc[g] = s;
        mx = fmaxf(mx, s);
    }
    float sum = 0.0f;
#pragma unroll
    for (int g = 0; g < HEADS; g++) {
        float e = __expf(sc[g] - mx);
        sc[g] = e;
        sum += e;
    }
    const float inv = 1.0f / sum;

    float acc[HD];
#pragma unroll
    for (int d = 0; d < HD; d++) acc[d] = 0.0f;
#pragma unroll
    for (int g = 0; g < HEADS; g++) {
        const float p = sc[g];
#pragma unroll
        for (int d = 0; d < HD; d++) acc[d] += p * vs[t][g][d];
    }

    __half* orow = out + row * DIM + h * HD;
#pragma unroll
    for (int c = 0; c < 4; c++) {
        __half2 o0 = __floats2half2_rn(acc[c*8+0] * inv, acc[c*8+1] * inv);
        __half2 o1 = __floats2half2_rn(acc[c*8+2] * inv, acc[c*8+3] * inv);
        __half2 o2 = __floats2half2_rn(acc[c*8+4] * inv, acc[c*8+5] * inv);
        __half2 o3 = __floats2half2_rn(acc[c*8+6] * inv, acc[c*8+7] * inv);
        uint4 p;
        p.x = *(uint32_t*)&o0; p.y = *(uint32_t*)&o1;
        p.z = *(uint32_t*)&o2; p.w = *(uint32_t*)&o3;
        *(uint4*)(orow + c * 8) = p;
    }
}

// ===================== Launch ===============================================
extern "C" void kernel_launch(void* const* d_in, const int* in_sizes, int n_in,
                              void* d_out, int out_size)
{
    const float* x      = (const float*)d_in[0];
    const float* ln1_g  = (const float*)d_in[1];
    const float* ln1_b  = (const float*)d_in[2];
    const float* qkv_w  = (const float*)d_in[3];
    const float* qkv_b  = (const float*)d_in[4];
    const float* proj_w = (const float*)d_in[5];
    const float* proj_b = (const float*)d_in[6];
    const float* ln2_g  = (const float*)d_in[7];
    const float* ln2_b  = (const float*)d_in[8];
    const float* ffn_w1 = (const float*)d_in[9];
    const float* ffn_b1 = (const float*)d_in[10];
    const float* ffn_w2 = (const float*)d_in[11];
    const float* ffn_b2 = (const float*)d_in[12];

    __half *xn, *qkv, *attn, *h, *w;
    float  *y;
    cudaGetSymbolAddress((void**)&xn,   g_xn);
    cudaGetSymbolAddress((void**)&qkv,  g_qkv);
    cudaGetSymbolAddress((void**)&attn, g_attn);
    cudaGetSymbolAddress((void**)&y,    g_y);
    cudaGetSymbolAddress((void**)&h,    g_h);
    cudaGetSymbolAddress((void**)&w,    g_w);
    float* out = (float*)d_out;

    const int MROWS = TOKENS / TILE;   // 512

    // 0) round weights to fp16 once per launch (deterministic)
    round_w<<<(196608/4 + 255)/256, 256>>>(qkv_w,  w + W_QKV,  196608/4);
    round_w<<<( 65536/4 + 255)/256, 256>>>(proj_w, w + W_PROJ,  65536/4);
    round_w<<<(262144/4 + 255)/256, 256>>>(ffn_w1, w + W_FFN1, 262144/4);
    round_w<<<(262144/4 + 255)/256, 256>>>(ffn_w2, w + W_FFN2, 262144/4);

    // 1) LN1 (half out)
    ln_kernel<<<TOKENS / 8, 256>>>(x, ln1_g, ln1_b, xn);
    // 2) QKV = xn @ qkv_w^T + qkv_b          [65536, 768] half
    mma_gemm<0, __half><<<dim3(768 / TILE, MROWS), 256>>>(
        xn, w + W_QKV, qkv_b, nullptr, qkv, DIM, 3 * DIM);
    // 3) per-token head-mixing attention (half out)
    attn_kernel<<<TOKENS / 16, 128>>>(qkv, attn);
    // 4) y = x + attn @ proj_w^T + proj_b    [65536, 256] f32
    mma_gemm<2, float><<<dim3(DIM / TILE, MROWS), 256>>>(
        attn, w + W_PROJ, proj_b, x, y, DIM, DIM);
    // 5) LN2 (half out)
    ln_kernel<<<TOKENS / 8, 256>>>(y, ln2_g, ln2_b, xn);
    // 6) h = relu(xn @ ffn_w1^T + ffn_b1)    [65536, 1024] half
    mma_gemm<1, __half><<<dim3(FFNDIM / TILE, MROWS), 256>>>(
        xn, w + W_FFN1, ffn_b1, nullptr, h, DIM, FFNDIM);
    // 7) out = y + h @ ffn_w2^T + ffn_b2     [65536, 256] f32
    mma_gemm<2, float><<<dim3(DIM / TILE, MROWS), 256>>>(
        h, w + W_FFN2, ffn_b2, y, out, FFNDIM, DIM);
}

// round 7
// speedup vs baseline: 5.1051x; 1.0036x over previous
#include <cuda_runtime.h>
#include <cuda_fp16.h>
#include <cstdint>

// ---------------------------------------------------------------------------
// SimpleMaxViTBlock: LN1 -> per-token head-mixing attention -> +res
//                    -> LN2 -> FFN -> +res
// GEMMs: mma.sync m16n8k16 fp16, fp32 accum, 2 CTAs/SM.
// ---------------------------------------------------------------------------

constexpr int TOKENS = 65536;
constexpr int DIM    = 256;
constexpr int HEADS  = 8;
constexpr int HD     = 32;
constexpr int FFNDIM = 1024;

// Scratch (device globals: allocation-free rule)
__device__ __half g_xn  [ (size_t)TOKENS * DIM    ];
__device__ __half g_qkv [ (size_t)TOKENS * 3*DIM  ];
__device__ __half g_attn[ (size_t)TOKENS * DIM    ];
__device__ float  g_y   [ (size_t)TOKENS * DIM    ];
__device__ __half g_h   [ (size_t)TOKENS * FFNDIM ];
__device__ __half g_w   [ 786432 ];   // fp16-rounded weights

constexpr int W_QKV  = 0;
constexpr int W_PROJ = 196608;
constexpr int W_FFN1 = 262144;
constexpr int W_FFN2 = 524288;

// ===================== helpers ==============================================
__device__ __forceinline__ uint32_t smem_u32(const void* p) {
    uint32_t a;
    asm("{ .reg .u64 t; cvta.to.shared.u64 t, %1; cvt.u32.u64 %0, t; }"
        : "=r"(a) : "l"(p));
    return a;
}
__device__ __forceinline__ void cp_async16(uint32_t saddr, const void* gaddr) {
    asm volatile("cp.async.cg.shared.global [%0], [%1], 16;"
                 :: "r"(saddr), "l"(gaddr) : "memory");
}
__device__ __forceinline__ void cp_commit() {
    asm volatile("cp.async.commit_group;" ::: "memory");
}
template<int N>
__device__ __forceinline__ void cp_wait() {
    asm volatile("cp.async.wait_group %0;" :: "n"(N) : "memory");
}
__device__ __forceinline__ void mma_f16(
    float& d0, float& d1, float& d2, float& d3,
    uint32_t a0, uint32_t a1, uint32_t a2, uint32_t a3,
    uint32_t b0, uint32_t b1)
{
    asm volatile(
        "mma.sync.aligned.m16n8k16.row.col.f32.f16.f16.f32 "
        "{%0,%1,%2,%3}, {%4,%5,%6,%7}, {%8,%9}, {%0,%1,%2,%3};"
        : "+f"(d0), "+f"(d1), "+f"(d2), "+f"(d3)
        : "r"(a0), "r"(a1), "r"(a2), "r"(a3), "r"(b0), "r"(b1));
}

// ===================== fp16 mma.sync GEMM ===================================
// C[m,n] = epi( sum_k A[m,k]*B[n,k] + bias[n] [+res] )
// A:[M,K], B:[N,K] row-major __half. CTA 128x128, BK=32 (halves),
// double-buffered cp.async, 8 warps (4M x 2N), warp 32x64, 2 CTAs/SM.
// Row stride in smem: 40 halves = 20 u32 (conflict-free fragment loads).
// MODE: 0 = bias -> half out, 1 = bias+relu -> half out, 2 = bias+res -> f32
constexpr int TILE  = 128;
constexpr int BK    = 32;
constexpr int LDU   = 20;              // u32 per smem row (= 40 halves)
constexpr int SLABU = TILE * LDU;      // 2560 u32 per stage per matrix

template<int MODE, typename OutT>
__global__ void __launch_bounds__(256, 2) mma_gemm(
    const __half* __restrict__ A, const __half* __restrict__ B,
    const float* __restrict__ bias, const float* __restrict__ res,
    OutT* __restrict__ C, int K, int N)
{
    __shared__ __align__(16) uint32_t sm[4 * SLABU];   // 40960 B
    uint32_t* As = sm;                  // [2][128][20]
    uint32_t* Bs = sm + 2 * SLABU;
    const uint32_t As_u = smem_u32(As);
    const uint32_t Bs_u = smem_u32(Bs);

    const int tid  = threadIdx.x;
    const int wid  = tid >> 5;
    const int lane = tid & 31;
    const int gid  = lane >> 2;     // 0..7
    const int tg   = lane & 3;      // 0..3

    const int bm = blockIdx.y * TILE;
    const int bn = blockIdx.x * TILE;
    const int m_off = (wid >> 1) * 32;
    const int n_off = (wid & 1) * 64;

    // cp.async mapping: 512 16B-transfers per matrix, 256 threads x 2 iters
    const int crow = tid >> 2;          // +64 per it
    const int cc8  = (tid & 3) * 8;     // half offset within 32-half row

    float d[2][8][4];
#pragma unroll
    for (int mt = 0; mt < 2; mt++)
#pragma unroll
        for (int nt = 0; nt < 8; nt++)
#pragma unroll
            for (int j = 0; j < 4; j++) d[mt][nt][j] = 0.0f;

    const int C_CHUNKS = K / BK;

    // stage 0
    {
#pragma unroll
        for (int it = 0; it < 2; it++) {
            int row = crow + it * 64;
            cp_async16(As_u + (uint32_t)(row * LDU + cc8 / 2) * 4,
                       A + (size_t)(bm + row) * K + cc8);
            cp_async16(Bs_u + (uint32_t)(row * LDU + cc8 / 2) * 4,
                       B + (size_t)(bn + row) * K + cc8);
        }
        cp_commit();
    }

    for (int c = 0; c < C_CHUNKS; c++) {
        const int buf = c & 1;
        if (c + 1 < C_CHUNKS) {
            const int nb  = (c + 1) & 1;
            const int k0g = (c + 1) * BK;
#pragma unroll
            for (int it = 0; it < 2; it++) {
                int row = crow + it * 64;
                cp_async16(As_u + (uint32_t)((nb * SLABU + row * LDU + cc8 / 2) * 4),
                           A + (size_t)(bm + row) * K + k0g + cc8);
                cp_async16(Bs_u + (uint32_t)((nb * SLABU + row * LDU + cc8 / 2) * 4),
                           B + (size_t)(bn + row) * K + k0g + cc8);
            }
            cp_commit();
            cp_wait<1>();
        } else {
            cp_wait<0>();
        }
        __syncthreads();

        const uint32_t* Ab = As + buf * SLABU;
        const uint32_t* Bb = Bs + buf * SLABU;

        // 2 k-steps of 16 (single fragment buffer; ptxas schedules LDS ahead)
#pragma unroll
        for (int ks = 0; ks < 2; ks++) {
            const int ko = ks * 8;
            uint32_t a[2][4], b[8][2];
#pragma unroll
            for (int mt = 0; mt < 2; mt++) {
                const int r0 = m_off + mt * 16 + gid;
                a[mt][0] = Ab[(r0)     * LDU + ko + tg];
                a[mt][1] = Ab[(r0 + 8) * LDU + ko + tg];
                a[mt][2] = Ab[(r0)     * LDU + ko + tg + 4];
                a[mt][3] = Ab[(r0 + 8) * LDU + ko + tg + 4];
            }
#pragma unroll
            for (int nt = 0; nt < 8; nt++) {
                const int c0 = n_off + nt * 8 + gid;
                b[nt][0] = Bb[c0 * LDU + ko + tg];
                b[nt][1] = Bb[c0 * LDU + ko + tg + 4];
            }
#pragma unroll
            for (int mt = 0; mt < 2; mt++)
#pragma unroll
                for (int nt = 0; nt < 8; nt++)
                    mma_f16(d[mt][nt][0], d[mt][nt][1], d[mt][nt][2], d[mt][nt][3],
                            a[mt][0], a[mt][1], a[mt][2], a[mt][3],
                            b[nt][0], b[nt][1]);
        }
        __syncthreads();
    }

    // ---- epilogue ----
#pragma unroll
    for (int nt = 0; nt < 8; nt++) {
        const int n = bn + n_off + nt * 8 + 2 * tg;
        const float2 bv = *(const float2*)&bias[n];
#pragma unroll
        for (int mt = 0; mt < 2; mt++) {
            const int m0 = bm + m_off + mt * 16 + gid;
#pragma unroll
            for (int half_i = 0; half_i < 2; half_i++) {
                const int m = m0 + half_i * 8;
                float vx = d[mt][nt][half_i * 2 + 0] + bv.x;
                float vy = d[mt][nt][half_i * 2 + 1] + bv.y;
                if (MODE == 1) { vx = fmaxf(vx, 0.f); vy = fmaxf(vy, 0.f); }
                if (MODE == 2) {
                    const float2 r = *(const float2*)&res[(size_t)m * N + n];
                    float2 v; v.x = vx + r.x; v.y = vy + r.y;
                    *(float2*)&((float*)C)[(size_t)m * N + n] = v;
                } else {
                    *(__half2*)&((__half*)C)[(size_t)m * N + n] =
                        __floats2half2_rn(vx, vy);
                }
            }
        }
    }
}

// ===================== weight rounding (all four, one launch) ===============
__global__ void __launch_bounds__(256) round_w_all(
    const float* __restrict__ qkv_w, const float* __restrict__ proj_w,
    const float* __restrict__ ffn_w1, const float* __restrict__ ffn_w2,
    __half* __restrict__ dst)
{
    int i = blockIdx.x * 256 + threadIdx.x;          // float4 index, 196608 total
    const float* src;
    int local;
    if (i < 49152)       { src = qkv_w;  local = i;           }
    else if (i < 65536)  { src = proj_w; local = i - 49152;   }
    else if (i < 131072) { src = ffn_w1; local = i - 65536;   }
    else                 { src = ffn_w2; local = i - 131072;  }
    float4 v = ((const float4*)src)[local];
    __half2 lo = __floats2half2_rn(v.x, v.y);
    __half2 hi = __floats2half2_rn(v.z, v.w);
    uint2 o; o.x = *(uint32_t*)&lo; o.y = *(uint32_t*)&hi;
    ((uint2*)dst)[i] = o;
}

// ===================== LayerNorm (one warp per 256-float row) ===============
__global__ void __launch_bounds__(256) ln_kernel(
    const float* __restrict__ x, const float* __restrict__ g,
    const float* __restrict__ b, __half* __restrict__ out)
{
    int row  = (blockIdx.x * blockDim.x + threadIdx.x) >> 5;
    int lane = threadIdx.x & 31;
    const float4* xr = (const float4*)(x + (size_t)row * DIM);
    float4 v0 = xr[lane];
    float4 v1 = xr[lane + 32];

    float s = v0.x + v0.y + v0.z + v0.w + v1.x + v1.y + v1.z + v1.w;
    float q = v0.x*v0.x + v0.y*v0.y + v0.z*v0.z + v0.w*v0.w
            + v1.x*v1.x + v1.y*v1.y + v1.z*v1.z + v1.w*v1.w;
#pragma unroll
    for (int o = 16; o > 0; o >>= 1) {
        s += __shfl_xor_sync(0xffffffffu, s, o);
        q += __shfl_xor_sync(0xffffffffu, q, o);
    }
    float mean = s * (1.0f / 256.0f);
    float var  = q * (1.0f / 256.0f) - mean * mean;
    float inv  = rsqrtf(var + 1e-5f);

    const float4* g4 = (const float4*)g;
    const float4* b4 = (const float4*)b;
    float4 ga = g4[lane], gb = g4[lane + 32];
    float4 ba = b4[lane], bb = b4[lane + 32];

    __half2 h0 = __floats2half2_rn((v0.x - mean) * inv * ga.x + ba.x,
                                   (v0.y - mean) * inv * ga.y + ba.y);
    __half2 h1 = __floats2half2_rn((v0.z - mean) * inv * ga.z + ba.z,
                                   (v0.w - mean) * inv * ga.w + ba.w);
    __half2 h2 = __floats2half2_rn((v1.x - mean) * inv * gb.x + bb.x,
                                   (v1.y - mean) * inv * gb.y + bb.y);
    __half2 h3 = __floats2half2_rn((v1.z - mean) * inv * gb.z + bb.z,
                                   (v1.w - mean) * inv * gb.w + bb.w);

    __half* orow = out + (size_t)row * DIM;
    uint2 p0; p0.x = *(uint32_t*)&h0; p0.y = *(uint32_t*)&h1;
    uint2 p1; p1.x = *(uint32_t*)&h2; p1.y = *(uint32_t*)&h3;
    *(uint2*)(orow + lane * 4)       = p0;
    *(uint2*)(orow + 128 + lane * 4) = p1;
}

// ===================== Per-token head-mixing attention ======================
__global__ void __launch_bounds__(128) attn_kernel(
    const __half* __restrict__ qkv, __half* __restrict__ out)
{
    __shared__ __align__(16) float ks[16][HEADS][HD + 1];
    __shared__ __align__(16) float vs[16][HEADS][HD + 1];

    const int tok0 = blockIdx.x * 16;
    const int tid  = threadIdx.x;

#pragma unroll
    for (int it = 0; it < 4; it++) {
        int fi = tid + it * 128;            // 0..511
        int t  = fi >> 5;
        int c  = fi & 31;
        int g  = c >> 2;
        int d  = (c & 3) * 8;
        const __half* base = qkv + (size_t)(tok0 + t) * 768;
        uint4 kv = *(const uint4*)(base + 256 + g * HD + d);
        uint4 vv = *(const uint4*)(base + 512 + g * HD + d);
        const __half2* kh = (const __half2*)&kv;
        const __half2* vh = (const __half2*)&vv;
#pragma unroll
        for (int j = 0; j < 4; j++) {
            float2 kf = __half22float2(kh[j]);
            float2 vf = __half22float2(vh[j]);
            ks[t][g][d + 2*j]     = kf.x;
            ks[t][g][d + 2*j + 1] = kf.y;
            vs[t][g][d + 2*j]     = vf.x;
            vs[t][g][d + 2*j + 1] = vf.y;
        }
    }
    __syncthreads();

    const int t = tid >> 3;
    const int h = tid & 7;
    const size_t row = (size_t)(tok0 + t);

    float q[HD];
    {
        const __half* qrow = qkv + row * 768 + h * HD;
#pragma unroll
        for (int c = 0; c < 4; c++) {
            uint4 qv = *(const uint4*)(qrow + c * 8);
            const __half2* qh = (const __half2*)&qv;
#pragma unroll
            for (int j = 0; j < 4; j++) {
                float2 qf = __half22float2(qh[j]);
                q[c * 8 + 2*j]     = qf.x;
                q[c * 8 + 2*j + 1] = qf.y;
            }
        }
    }

    const float scale = 0.17677669529663688f;   // 1/sqrt(32)
    float sc[HEADS];
    float mx = -1e30f;
#pragma unroll
    for (int g = 0; g < HEADS; g++) {
        float s = 0.0f;
#pragma unroll
        for (int d = 0; d < HD; d++) s += q[d] * ks[t][g][d];
        s *= scale;
        sc[g] = s;
        mx = fmaxf(mx, s);
    }
    float sum = 0.0f;
#pragma unroll
    for (int g = 0; g < HEADS; g++) {
        float e = __expf(sc[g] - mx);
        sc[g] = e;
        sum += e;
    }
    const float inv = 1.0f / sum;

    float acc[HD];
#pragma unroll
    for (int d = 0; d < HD; d++) acc[d] = 0.0f;
#pragma unroll
    for (int g = 0; g < HEADS; g++) {
        const float p = sc[g];
#pragma unroll
        for (int d = 0; d < HD; d++) acc[d] += p * vs[t][g][d];
    }

    __half* orow = out + row * DIM + h * HD;
#pragma unroll
    for (int c = 0; c < 4; c++) {
        __half2 o0 = __floats2half2_rn(acc[c*8+0] * inv, acc[c*8+1] * inv);
        __half2 o1 = __floats2half2_rn(acc[c*8+2] * inv, acc[c*8+3] * inv);
        __half2 o2 = __floats2half2_rn(acc[c*8+4] * inv, acc[c*8+5] * inv);
        __half2 o3 = __floats2half2_rn(acc[c*8+6] * inv, acc[c*8+7] * inv);
        uint4 p;
        p.x = *(uint32_t*)&o0; p.y = *(uint32_t*)&o1;
        p.z = *(uint32_t*)&o2; p.w = *(uint32_t*)&o3;
        *(uint4*)(orow + c * 8) = p;
    }
}

// ===================== Launch ===============================================
extern "C" void kernel_launch(void* const* d_in, const int* in_sizes, int n_in,
                              void* d_out, int out_size)
{
    const float* x      = (const float*)d_in[0];
    const float* ln1_g  = (const float*)d_in[1];
    const float* ln1_b  = (const float*)d_in[2];
    const float* qkv_w  = (const float*)d_in[3];
    const float* qkv_b  = (const float*)d_in[4];
    const float* proj_w = (const float*)d_in[5];
    const float* proj_b = (const float*)d_in[6];
    const float* ln2_g  = (const float*)d_in[7];
    const float* ln2_b  = (const float*)d_in[8];
    const float* ffn_w1 = (const float*)d_in[9];
    const float* ffn_b1 = (const float*)d_in[10];
    const float* ffn_w2 = (const float*)d_in[11];
    const float* ffn_b2 = (const float*)d_in[12];

    __half *xn, *qkv, *attn, *h, *w;
    float  *y;
    cudaGetSymbolAddress((void**)&xn,   g_xn);
    cudaGetSymbolAddress((void**)&qkv,  g_qkv);
    cudaGetSymbolAddress((void**)&attn, g_attn);
    cudaGetSymbolAddress((void**)&y,    g_y);
    cudaGetSymbolAddress((void**)&h,    g_h);
    cudaGetSymbolAddress((void**)&w,    g_w);
    float* out = (float*)d_out;

    const int MROWS = TOKENS / TILE;   // 512

    // 0) round all weights to fp16 in one launch (196608 float4s)
    round_w_all<<<196608 / 256, 256>>>(qkv_w, proj_w, ffn_w1, ffn_w2, w);

    // 1) LN1 (half out)
    ln_kernel<<<TOKENS / 8, 256>>>(x, ln1_g, ln1_b, xn);
    // 2) QKV = xn @ qkv_w^T + qkv_b          [65536, 768] half
    mma_gemm<0, __half><<<dim3(768 / TILE, MROWS), 256>>>(
        xn, w + W_QKV, qkv_b, nullptr, qkv, DIM, 3 * DIM);
    // 3) per-token head-mixing attention (half out)
    attn_kernel<<<TOKENS / 16, 128>>>(qkv, attn);
    // 4) y = x + attn @ proj_w^T + proj_b    [65536, 256] f32
    mma_gemm<2, float><<<dim3(DIM / TILE, MROWS), 256>>>(
        attn, w + W_PROJ, proj_b, x, y, DIM, DIM);
    // 5) LN2 (half out)
    ln_kernel<<<TOKENS / 8, 256>>>(y, ln2_g, ln2_b, xn);
    // 6) h = relu(xn @ ffn_w1^T + ffn_b1)    [65536, 1024] half
    mma_gemm<1, __half><<<dim3(FFNDIM / TILE, MROWS), 256>>>(
        xn, w + W_FFN1, ffn_b1, nullptr, h, DIM, FFNDIM);
    // 7) out = y + h @ ffn_w2^T + ffn_b2     [65536, 256] f32
    mma_gemm<2, float><<<dim3(DIM / TILE, MROWS), 256>>>(
        h, w + W_FFN2, ffn_b2, y, out, FFNDIM, DIM);
}

// round 8
// speedup vs baseline: 5.6083x; 1.0985x over previous
#include <cuda_runtime.h>
#include <cuda_fp16.h>
#include <cstdint>

// ---------------------------------------------------------------------------
// SimpleMaxViTBlock: LN1 -> per-token head-mixing attention -> +res
//                    -> LN2 -> FFN -> +res
// GEMMs: mma.sync m16n8k16 fp16, fp32 accum. ldmatrix fragment loads,
// 4 warps/CTA (2x2), warp tile 64x64, 2 CTAs/SM.
// ---------------------------------------------------------------------------

constexpr int TOKENS = 65536;
constexpr int DIM    = 256;
constexpr int HEADS  = 8;
constexpr int HD     = 32;
constexpr int FFNDIM = 1024;

// Scratch (device globals: allocation-free rule)
__device__ __half g_xn  [ (size_t)TOKENS * DIM    ];
__device__ __half g_qkv [ (size_t)TOKENS * 3*DIM  ];
__device__ __half g_attn[ (size_t)TOKENS * DIM    ];
__device__ float  g_y   [ (size_t)TOKENS * DIM    ];
__device__ __half g_h   [ (size_t)TOKENS * FFNDIM ];
__device__ __half g_w   [ 786432 ];   // fp16-rounded weights

constexpr int W_QKV  = 0;
constexpr int W_PROJ = 196608;
constexpr int W_FFN1 = 262144;
constexpr int W_FFN2 = 524288;

// ===================== helpers ==============================================
__device__ __forceinline__ uint32_t smem_u32(const void* p) {
    uint32_t a;
    asm("{ .reg .u64 t; cvta.to.shared.u64 t, %1; cvt.u32.u64 %0, t; }"
        : "=r"(a) : "l"(p));
    return a;
}
__device__ __forceinline__ void cp_async16(uint32_t saddr, const void* gaddr) {
    asm volatile("cp.async.cg.shared.global [%0], [%1], 16;"
                 :: "r"(saddr), "l"(gaddr) : "memory");
}
__device__ __forceinline__ void cp_commit() {
    asm volatile("cp.async.commit_group;" ::: "memory");
}
template<int N>
__device__ __forceinline__ void cp_wait() {
    asm volatile("cp.async.wait_group %0;" :: "n"(N) : "memory");
}
__device__ __forceinline__ void ldm_x4(uint32_t& r0, uint32_t& r1,
                                       uint32_t& r2, uint32_t& r3, uint32_t addr) {
    asm volatile("ldmatrix.sync.aligned.m8n8.x4.shared.b16 {%0,%1,%2,%3}, [%4];"
                 : "=r"(r0), "=r"(r1), "=r"(r2), "=r"(r3) : "r"(addr));
}
__device__ __forceinline__ void mma_f16(
    float& d0, float& d1, float& d2, float& d3,
    uint32_t a0, uint32_t a1, uint32_t a2, uint32_t a3,
    uint32_t b0, uint32_t b1)
{
    asm volatile(
        "mma.sync.aligned.m16n8k16.row.col.f32.f16.f16.f32 "
        "{%0,%1,%2,%3}, {%4,%5,%6,%7}, {%8,%9}, {%0,%1,%2,%3};"
        : "+f"(d0), "+f"(d1), "+f"(d2), "+f"(d3)
        : "r"(a0), "r"(a1), "r"(a2), "r"(a3), "r"(b0), "r"(b1));
}

// ===================== fp16 mma.sync GEMM ===================================
// C[m,n] = epi( sum_k A[m,k]*B[n,k] + bias[n] [+res] )
// A:[M,K], B:[N,K] row-major __half. CTA 128x128, BK=32 halves,
// double-buffered cp.async, 4 warps (2x2), warp tile 64x64, ldmatrix frags.
// smem row stride: 40 halves = 20 u32 = 80B (conflict-free for ldmatrix).
// MODE: 0 = bias -> half out, 1 = bias+relu -> half out, 2 = bias+res -> f32
constexpr int TILE  = 128;
constexpr int BK    = 32;
constexpr int LDU   = 20;              // u32 per smem row (= 40 halves, 80B)
constexpr int SLABU = TILE * LDU;      // 2560 u32 per stage per matrix

template<int MODE, typename OutT>
__global__ void __launch_bounds__(128, 2) mma_gemm(
    const __half* __restrict__ A, const __half* __restrict__ B,
    const float* __restrict__ bias, const float* __restrict__ res,
    OutT* __restrict__ C, int K, int N)
{
    __shared__ __align__(16) uint32_t sm[4 * SLABU];   // 40960 B
    uint32_t* As = sm;                  // [2][128][20]
    uint32_t* Bs = sm + 2 * SLABU;
    const uint32_t As_u = smem_u32(As);
    const uint32_t Bs_u = smem_u32(Bs);

    const int tid  = threadIdx.x;
    const int wid  = tid >> 5;
    const int lane = tid & 31;
    const int gid  = lane >> 2;     // 0..7
    const int tg   = lane & 3;      // 0..3

    const int bm = blockIdx.y * TILE;
    const int bn = blockIdx.x * TILE;
    const int m_off = (wid >> 1) * 64;   // 0 or 64
    const int n_off = (wid & 1) * 64;    // 0 or 64

    // ldmatrix per-lane address components
    const int lrow8 = lane & 7;          // row within 8x8 matrix
    const int a_row = (lrow8 + ((lane >> 3) & 1) * 8);          // A: bit3 -> +8 rows
    const int a_kof = (lane >> 4) * 4;                          // A: bit4 -> k+8
    const int b_row = (lrow8 + ((lane >> 4) & 1) * 8);          // B: bit4 -> +8 rows
    const int b_kof = ((lane >> 3) & 1) * 4;                    // B: bit3 -> k+8

    // cp.async mapping: 512 16B-transfers per matrix, 128 threads x 4 iters
    const int crow = tid >> 2;          // +32 per it
    const int cc4  = (tid & 3) * 4;     // u32 offset within 16 u32 of row data

    float d[4][8][4];
#pragma unroll
    for (int mt = 0; mt < 4; mt++)
#pragma unroll
        for (int nt = 0; nt < 8; nt++)
#pragma unroll
            for (int j = 0; j < 4; j++) d[mt][nt][j] = 0.0f;

    const int C_CHUNKS = K / BK;

    // stage 0
    {
#pragma unroll
        for (int it = 0; it < 4; it++) {
            int row = crow + it * 32;
            cp_async16(As_u + (uint32_t)(row * LDU + cc4) * 4,
                       A + (size_t)(bm + row) * K + cc4 * 2);
            cp_async16(Bs_u + (uint32_t)(row * LDU + cc4) * 4,
                       B + (size_t)(bn + row) * K + cc4 * 2);
        }
        cp_commit();
    }

    for (int c = 0; c < C_CHUNKS; c++) {
        const int buf = c & 1;
        if (c + 1 < C_CHUNKS) {
            const int nb  = (c + 1) & 1;
            const int k0g = (c + 1) * BK;
#pragma unroll
            for (int it = 0; it < 4; it++) {
                int row = crow + it * 32;
                cp_async16(As_u + (uint32_t)((nb * SLABU + row * LDU + cc4) * 4),
                           A + (size_t)(bm + row) * K + k0g + cc4 * 2);
                cp_async16(Bs_u + (uint32_t)((nb * SLABU + row * LDU + cc4) * 4),
                           B + (size_t)(bn + row) * K + k0g + cc4 * 2);
            }
            cp_commit();
            cp_wait<1>();
        } else {
            cp_wait<0>();
        }
        __syncthreads();

        const uint32_t Ab = As_u + (uint32_t)(buf * SLABU) * 4;
        const uint32_t Bb = Bs_u + (uint32_t)(buf * SLABU) * 4;

#pragma unroll
        for (int ks = 0; ks < 2; ks++) {
            const int ko = ks * 8;      // u32 offset (16 halves per k-step)

            uint32_t a[4][4];
#pragma unroll
            for (int mt = 0; mt < 4; mt++) {
                uint32_t addr = Ab + (uint32_t)(
                    (m_off + mt * 16 + a_row) * LDU + ko + a_kof) * 4;
                ldm_x4(a[mt][0], a[mt][1], a[mt][2], a[mt][3], addr);
            }
            uint32_t b[8][2];
#pragma unroll
            for (int np = 0; np < 4; np++) {
                uint32_t addr = Bb + (uint32_t)(
                    (n_off + np * 16 + b_row) * LDU + ko + b_kof) * 4;
                ldm_x4(b[2*np][0], b[2*np][1], b[2*np+1][0], b[2*np+1][1], addr);
            }
#pragma unroll
            for (int mt = 0; mt < 4; mt++)
#pragma unroll
                for (int nt = 0; nt < 8; nt++)
                    mma_f16(d[mt][nt][0], d[mt][nt][1], d[mt][nt][2], d[mt][nt][3],
                            a[mt][0], a[mt][1], a[mt][2], a[mt][3],
                            b[nt][0], b[nt][1]);
        }
        __syncthreads();
    }

    // ---- epilogue ----
#pragma unroll
    for (int nt = 0; nt < 8; nt++) {
        const int n = bn + n_off + nt * 8 + 2 * tg;
        const float2 bv = *(const float2*)&bias[n];
#pragma unroll
        for (int mt = 0; mt < 4; mt++) {
            const int m0 = bm + m_off + mt * 16 + gid;
#pragma unroll
            for (int half_i = 0; half_i < 2; half_i++) {
                const int m = m0 + half_i * 8;
                float vx = d[mt][nt][half_i * 2 + 0] + bv.x;
                float vy = d[mt][nt][half_i * 2 + 1] + bv.y;
                if (MODE == 1) { vx = fmaxf(vx, 0.f); vy = fmaxf(vy, 0.f); }
                if (MODE == 2) {
                    const float2 r = *(const float2*)&res[(size_t)m * N + n];
                    float2 v; v.x = vx + r.x; v.y = vy + r.y;
                    *(float2*)&((float*)C)[(size_t)m * N + n] = v;
                } else {
                    *(__half2*)&((__half*)C)[(size_t)m * N + n] =
                        __floats2half2_rn(vx, vy);
                }
            }
        }
    }
}

// ===================== weight rounding (all four, one launch) ===============
__global__ void __launch_bounds__(256) round_w_all(
    const float* __restrict__ qkv_w, const float* __restrict__ proj_w,
    const float* __restrict__ ffn_w1, const float* __restrict__ ffn_w2,
    __half* __restrict__ dst)
{
    int i = blockIdx.x * 256 + threadIdx.x;          // float4 index, 196608 total
    const float* src;
    int local;
    if (i < 49152)       { src = qkv_w;  local = i;           }
    else if (i < 65536)  { src = proj_w; local = i - 49152;   }
    else if (i < 131072) { src = ffn_w1; local = i - 65536;   }
    else                 { src = ffn_w2; local = i - 131072;  }
    float4 v = ((const float4*)src)[local];
    __half2 lo = __floats2half2_rn(v.x, v.y);
    __half2 hi = __floats2half2_rn(v.z, v.w);
    uint2 o; o.x = *(uint32_t*)&lo; o.y = *(uint32_t*)&hi;
    ((uint2*)dst)[i] = o;
}

// ===================== LayerNorm (one warp per 256-float row) ===============
__global__ void __launch_bounds__(256) ln_kernel(
    const float* __restrict__ x, const float* __restrict__ g,
    const float* __restrict__ b, __half* __restrict__ out)
{
    int row  = (blockIdx.x * blockDim.x + threadIdx.x) >> 5;
    int lane = threadIdx.x & 31;
    const float4* xr = (const float4*)(x + (size_t)row * DIM);
    float4 v0 = xr[lane];
    float4 v1 = xr[lane + 32];

    float s = v0.x + v0.y + v0.z + v0.w + v1.x + v1.y + v1.z + v1.w;
    float q = v0.x*v0.x + v0.y*v0.y + v0.z*v0.z + v0.w*v0.w
            + v1.x*v1.x + v1.y*v1.y + v1.z*v1.z + v1.w*v1.w;
#pragma unroll
    for (int o = 16; o > 0; o >>= 1) {
        s += __shfl_xor_sync(0xffffffffu, s, o);
        q += __shfl_xor_sync(0xffffffffu, q, o);
    }
    float mean = s * (1.0f / 256.0f);
    float var  = q * (1.0f / 256.0f) - mean * mean;
    float inv  = rsqrtf(var + 1e-5f);

    const float4* g4 = (const float4*)g;
    const float4* b4 = (const float4*)b;
    float4 ga = g4[lane], gb = g4[lane + 32];
    float4 ba = b4[lane], bb = b4[lane + 32];

    __half2 h0 = __floats2half2_rn((v0.x - mean) * inv * ga.x + ba.x,
                                   (v0.y - mean) * inv * ga.y + ba.y);
    __half2 h1 = __floats2half2_rn((v0.z - mean) * inv * ga.z + ba.z,
                                   (v0.w - mean) * inv * ga.w + ba.w);
    __half2 h2 = __floats2half2_rn((v1.x - mean) * inv * gb.x + bb.x,
                                   (v1.y - mean) * inv * gb.y + bb.y);
    __half2 h3 = __floats2half2_rn((v1.z - mean) * inv * gb.z + bb.z,
                                   (v1.w - mean) * inv * gb.w + bb.w);

    __half* orow = out + (size_t)row * DIM;
    uint2 p0; p0.x = *(uint32_t*)&h0; p0.y = *(uint32_t*)&h1;
    uint2 p1; p1.x = *(uint32_t*)&h2; p1.y = *(uint32_t*)&h3;
    *(uint2*)(orow + lane * 4)       = p0;
    *(uint2*)(orow + 128 + lane * 4) = p1;
}

// ===================== Per-token head-mixing attention ======================
__global__ void __launch_bounds__(128) attn_kernel(
    const __half* __restrict__ qkv, __half* __restrict__ out)
{
    __shared__ __align__(16) float ks[16][HEADS][HD + 1];
    __shared__ __align__(16) float vs[16][HEADS][HD + 1];

    const int tok0 = blockIdx.x * 16;
    const int tid  = threadIdx.x;

#pragma unroll
    for (int it = 0; it < 4; it++) {
        int fi = tid + it * 128;            // 0..511
        int t  = fi >> 5;
        int c  = fi & 31;
        int g  = c >> 2;
        int d  = (c & 3) * 8;
        const __half* base = qkv + (size_t)(tok0 + t) * 768;
        uint4 kv = *(const uint4*)(base + 256 + g * HD + d);
        uint4 vv = *(const uint4*)(base + 512 + g * HD + d);
        const __half2* kh = (const __half2*)&kv;
        const __half2* vh = (const __half2*)&vv;
#pragma unroll
        for (int j = 0; j < 4; j++) {
            float2 kf = __half22float2(kh[j]);
            float2 vf = __half22float2(vh[j]);
            ks[t][g][d + 2*j]     = kf.x;
            ks[t][g][d + 2*j + 1] = kf.y;
            vs[t][g][d + 2*j]     = vf.x;
            vs[t][g][d + 2*j + 1] = vf.y;
        }
    }
    __syncthreads();

    const int t = tid >> 3;
    const int h = tid & 7;
    const size_t row = (size_t)(tok0 + t);

    float q[HD];
    {
        const __half* qrow = qkv + row * 768 + h * HD;
#pragma unroll
        for (int c = 0; c < 4; c++) {
            uint4 qv = *(const uint4*)(qrow + c * 8);
            const __half2* qh = (const __half2*)&qv;
#pragma unroll
            for (int j = 0; j < 4; j++) {
                float2 qf = __half22float2(qh[j]);
                q[c * 8 + 2*j]     = qf.x;
                q[c * 8 + 2*j + 1] = qf.y;
            }
        }
    }

    const float scale = 0.17677669529663688f;   // 1/sqrt(32)
    float sc[HEADS];
    float mx = -1e30f;
#pragma unroll
    for (int g = 0; g < HEADS; g++) {
        float s = 0.0f;
#pragma unroll
        for (int d = 0; d < HD; d++) s += q[d] * ks[t][g][d];
        s *= scale;
        sc[g] = s;
        mx = fmaxf(mx, s);
    }
    float sum = 0.0f;
#pragma unroll
    for (int g = 0; g < HEADS; g++) {
        float e = __expf(sc[g] - mx);
        sc[g] = e;
        sum += e;
    }
    const float inv = 1.0f / sum;

    float acc[HD];
#pragma unroll
    for (int d = 0; d < HD; d++) acc[d] = 0.0f;
#pragma unroll
    for (int g = 0; g < HEADS; g++) {
        const float p = sc[g];
#pragma unroll
        for (int d = 0; d < HD; d++) acc[d] += p * vs[t][g][d];
    }

    __half* orow = out + row * DIM + h * HD;
#pragma unroll
    for (int c = 0; c < 4; c++) {
        __half2 o0 = __floats2half2_rn(acc[c*8+0] * inv, acc[c*8+1] * inv);
        __half2 o1 = __floats2half2_rn(acc[c*8+2] * inv, acc[c*8+3] * inv);
        __half2 o2 = __floats2half2_rn(acc[c*8+4] * inv, acc[c*8+5] * inv);
        __half2 o3 = __floats2half2_rn(acc[c*8+6] * inv, acc[c*8+7] * inv);
        uint4 p;
        p.x = *(uint32_t*)&o0; p.y = *(uint32_t*)&o1;
        p.z = *(uint32_t*)&o2; p.w = *(uint32_t*)&o3;
        *(uint4*)(orow + c * 8) = p;
    }
}

// ===================== Launch ===============================================
extern "C" void kernel_launch(void* const* d_in, const int* in_sizes, int n_in,
                              void* d_out, int out_size)
{
    const float* x      = (const float*)d_in[0];
    const float* ln1_g  = (const float*)d_in[1];
    const float* ln1_b  = (const float*)d_in[2];
    const float* qkv_w  = (const float*)d_in[3];
    const float* qkv_b  = (const float*)d_in[4];
    const float* proj_w = (const float*)d_in[5];
    const float* proj_b = (const float*)d_in[6];
    const float* ln2_g  = (const float*)d_in[7];
    const float* ln2_b  = (const float*)d_in[8];
    const float* ffn_w1 = (const float*)d_in[9];
    const float* ffn_b1 = (const float*)d_in[10];
    const float* ffn_w2 = (const float*)d_in[11];
    const float* ffn_b2 = (const float*)d_in[12];

    __half *xn, *qkv, *attn, *h, *w;
    float  *y;
    cudaGetSymbolAddress((void**)&xn,   g_xn);
    cudaGetSymbolAddress((void**)&qkv,  g_qkv);
    cudaGetSymbolAddress((void**)&attn, g_attn);
    cudaGetSymbolAddress((void**)&y,    g_y);
    cudaGetSymbolAddress((void**)&h,    g_h);
    cudaGetSymbolAddress((void**)&w,    g_w);
    float* out = (float*)d_out;

    const int MROWS = TOKENS / TILE;   // 512

    // 0) round all weights to fp16 in one launch (196608 float4s)
    round_w_all<<<196608 / 256, 256>>>(qkv_w, proj_w, ffn_w1, ffn_w2, w);

    // 1) LN1 (half out)
    ln_kernel<<<TOKENS / 8, 256>>>(x, ln1_g, ln1_b, xn);
    // 2) QKV = xn @ qkv_w^T + qkv_b          [65536, 768] half
    mma_gemm<0, __half><<<dim3(768 / TILE, MROWS), 128>>>(
        xn, w + W_QKV, qkv_b, nullptr, qkv, DIM, 3 * DIM);
    // 3) per-token head-mixing attention (half out)
    attn_kernel<<<TOKENS / 16, 128>>>(qkv, attn);
    // 4) y = x + attn @ proj_w^T + proj_b    [65536, 256] f32
    mma_gemm<2, float><<<dim3(DIM / TILE, MROWS), 128>>>(
        attn, w + W_PROJ, proj_b, x, y, DIM, DIM);
    // 5) LN2 (half out)
    ln_kernel<<<TOKENS / 8, 256>>>(y, ln2_g, ln2_b, xn);
    // 6) h = relu(xn @ ffn_w1^T + ffn_b1)    [65536, 1024] half
    mma_gemm<1, __half><<<dim3(FFNDIM / TILE, MROWS), 128>>>(
        xn, w + W_FFN1, ffn_b1, nullptr, h, DIM, FFNDIM);
    // 7) out = y + h @ ffn_w2^T + ffn_b2     [65536, 256] f32
    mma_gemm<2, float><<<dim3(DIM / TILE, MROWS), 128>>>(
        h, w + W_FFN2, ffn_b2, y, out, FFNDIM, DIM);
}